// round 12
// baseline (speedup 1.0000x reference)
#include <cuda_runtime.h>
#include <cuda_bf16.h>
#include <math.h>
#include <stdint.h>

// ---------------------------------------------------------------------------
// Problem constants
// ---------------------------------------------------------------------------
#define NL     12
#define DMODEL 768
#define NHEAD  12
#define DHEAD  64
#define FFDIM  3072
#define BATCH  2
#define QLEN   512
#define CLEN   2048
#define CHUNK  256
#define WINW   512
#define NQKV   2304
#define CROWS  (BATCH * CLEN)
#define QROWS  (BATCH * QLEN)
#define ROWSA  (CROWS + QROWS)
#define QBASE  CROWS

// ---------------------------------------------------------------------------
// PTX helpers
// ---------------------------------------------------------------------------
__device__ __forceinline__ uint32_t smem_u32(const void* p) {
    uint32_t a;
    asm("{ .reg .u64 t; cvta.to.shared.u64 t, %1; cvt.u32.u64 %0, t; }" : "=r"(a) : "l"(p));
    return a;
}
__device__ __forceinline__ void ldsm_x4(uint32_t* r, uint32_t addr) {
    asm volatile("ldmatrix.sync.aligned.m8n8.x4.shared.b16 {%0,%1,%2,%3}, [%4];"
                 : "=r"(r[0]), "=r"(r[1]), "=r"(r[2]), "=r"(r[3]) : "r"(addr));
}
__device__ __forceinline__ void ldsm_x4_trans(uint32_t* r, uint32_t addr) {
    asm volatile("ldmatrix.sync.aligned.m8n8.x4.trans.shared.b16 {%0,%1,%2,%3}, [%4];"
                 : "=r"(r[0]), "=r"(r[1]), "=r"(r[2]), "=r"(r[3]) : "r"(addr));
}
__device__ __forceinline__ void mma_bf16(float* c, const uint32_t* a, uint32_t b0, uint32_t b1) {
    asm volatile(
        "mma.sync.aligned.m16n8k16.row.col.f32.bf16.bf16.f32 "
        "{%0,%1,%2,%3}, {%4,%5,%6,%7}, {%8,%9}, {%0,%1,%2,%3};"
        : "+f"(c[0]), "+f"(c[1]), "+f"(c[2]), "+f"(c[3])
        : "r"(a[0]), "r"(a[1]), "r"(a[2]), "r"(a[3]), "r"(b0), "r"(b1));
}
#define CP_ASYNC16(dst, src) \
    asm volatile("cp.async.cg.shared.global [%0], [%1], 16;" :: "r"(dst), "l"(src))
#define CP_COMMIT() asm volatile("cp.async.commit_group;")
#define CP_WAIT(n)  asm volatile("cp.async.wait_group %0;" :: "n"(n))

// ---------------------------------------------------------------------------
// Scratch (device globals)
// ---------------------------------------------------------------------------
#define D2   ((size_t)DMODEL * DMODEL)
#define DF   ((size_t)DMODEL * FFDIM)
#define QKVW (3ull * D2)

__device__ __nv_bfloat16 g_wqkv_hi[12 * QKVW];
__device__ __nv_bfloat16 g_wqkv_lo[12 * QKVW];
__device__ __nv_bfloat16 g_wo_hi[12 * D2];
__device__ __nv_bfloat16 g_wo_lo[12 * D2];
__device__ __nv_bfloat16 g_w1_hi[12 * DF];
__device__ __nv_bfloat16 g_w1_lo[12 * DF];
__device__ __nv_bfloat16 g_w2_hi[12 * DF];
__device__ __nv_bfloat16 g_w2_lo[12 * DF];

__device__ float g_h [ROWSA * DMODEL];
__device__ __nv_bfloat16 g_h_hi[ROWSA * DMODEL];
__device__ __nv_bfloat16 g_h_lo[ROWSA * DMODEL];
__device__ float g_qkv[ROWSA * NQKV];
__device__ float g_t2 [ROWSA * DMODEL];
__device__ __nv_bfloat16 g_st_hi[ROWSA * DMODEL];
__device__ __nv_bfloat16 g_st_lo[ROWSA * DMODEL];
__device__ __nv_bfloat16 g_ffn_hi[ROWSA * FFDIM];
__device__ __nv_bfloat16 g_ffn_lo[ROWSA * FFDIM];

__device__ float g_sc [BATCH * CLEN * QLEN];
__device__ float g_re [BATCH * QLEN];

// ---------------------------------------------------------------------------
// Reductions
// ---------------------------------------------------------------------------
__device__ __forceinline__ float block_reduce_sum(float v) {
    __shared__ float sh[33];
    int lane = threadIdx.x & 31, wid = threadIdx.x >> 5;
    #pragma unroll
    for (int o = 16; o; o >>= 1) v += __shfl_xor_sync(0xffffffffu, v, o);
    if (lane == 0) sh[wid] = v;
    __syncthreads();
    if (wid == 0) {
        float t = (lane < 8) ? sh[lane] : 0.f;
        #pragma unroll
        for (int o = 4; o; o >>= 1) t += __shfl_xor_sync(0xffffffffu, t, o);
        if (lane == 0) sh[32] = t;
    }
    __syncthreads();
    float r = sh[32];
    __syncthreads();
    return r;
}
__device__ __forceinline__ float block_reduce_max(float v) {
    __shared__ float sh[33];
    int lane = threadIdx.x & 31, wid = threadIdx.x >> 5;
    #pragma unroll
    for (int o = 16; o; o >>= 1) v = fmaxf(v, __shfl_xor_sync(0xffffffffu, v, o));
    if (lane == 0) sh[wid] = v;
    __syncthreads();
    if (wid == 0) {
        float t = (lane < 8) ? sh[lane] : -1e30f;
        #pragma unroll
        for (int o = 4; o; o >>= 1) t = fmaxf(t, __shfl_xor_sync(0xffffffffu, t, o));
        if (lane == 0) sh[32] = t;
    }
    __syncthreads();
    float r = sh[32];
    __syncthreads();
    return r;
}

__device__ __forceinline__ void split_bf16(float x, __nv_bfloat16& hi, __nv_bfloat16& lo) {
    hi = __float2bfloat16(x);
    lo = __float2bfloat16(x - __bfloat162float(hi));
}
__device__ __forceinline__ void split_pack2(float a, float b, uint32_t& hi, uint32_t& lo) {
    __nv_bfloat16 ah, al, bh, bl;
    split_bf16(a, ah, al); split_bf16(b, bh, bl);
    __nv_bfloat162 H(ah, bh), L(al, bl);
    hi = *(uint32_t*)&H; lo = *(uint32_t*)&L;
}

// ---------------------------------------------------------------------------
// Batched weight transpose + split
// ---------------------------------------------------------------------------
__global__ void __launch_bounds__(256) wprep_qkv_all(
    const float* __restrict__ Wq, const float* __restrict__ Wk,
    const float* __restrict__ Wv,
    __nv_bfloat16* __restrict__ Thi, __nv_bfloat16* __restrict__ Tlo)
{
    __shared__ float t[32][33];
    int z = blockIdx.z;
    int l = z / 3, which = z % 3;
    const float* W = (which == 0 ? Wq : (which == 1 ? Wk : Wv)) + (size_t)l * D2;
    __nv_bfloat16* ohi = Thi + (size_t)l * QKVW + (size_t)which * D2;
    __nv_bfloat16* olo = Tlo + (size_t)l * QKVW + (size_t)which * D2;
    int tx = threadIdx.x & 31, ty = threadIdx.x >> 5;
    int n0 = blockIdx.x * 32, k0 = blockIdx.y * 32;
    #pragma unroll
    for (int j = 0; j < 4; j++)
        t[ty + 8 * j][tx] = W[(size_t)(k0 + ty + 8 * j) * DMODEL + n0 + tx];
    __syncthreads();
    #pragma unroll
    for (int j = 0; j < 4; j++) {
        int n = n0 + ty + 8 * j, k = k0 + tx;
        __nv_bfloat16 hi, lo;
        split_bf16(t[tx][ty + 8 * j], hi, lo);
        ohi[(size_t)n * DMODEL + k] = hi;
        olo[(size_t)n * DMODEL + k] = lo;
    }
}

__global__ void __launch_bounds__(256) wprep_b(
    const float* __restrict__ W, __nv_bfloat16* __restrict__ Thi,
    __nv_bfloat16* __restrict__ Tlo, int K, int N)
{
    __shared__ float t[32][33];
    size_t l = blockIdx.z;
    const float* Wl = W + l * (size_t)K * N;
    __nv_bfloat16* ohi = Thi + l * (size_t)K * N;
    __nv_bfloat16* olo = Tlo + l * (size_t)K * N;
    int tx = threadIdx.x & 31, ty = threadIdx.x >> 5;
    int n0 = blockIdx.x * 32, k0 = blockIdx.y * 32;
    #pragma unroll
    for (int j = 0; j < 4; j++)
        t[ty + 8 * j][tx] = Wl[(size_t)(k0 + ty + 8 * j) * N + n0 + tx];
    __syncthreads();
    #pragma unroll
    for (int j = 0; j < 4; j++) {
        int n = n0 + ty + 8 * j, k = k0 + tx;
        __nv_bfloat16 hi, lo;
        split_bf16(t[tx][ty + 8 * j], hi, lo);
        ohi[(size_t)n * K + k] = hi;
        olo[(size_t)n * K + k] = lo;
    }
}

// ---------------------------------------------------------------------------
// Merged embedding + LN / Add + LN
// ---------------------------------------------------------------------------
__global__ void __launch_bounds__(256) embed_ln_all(
    const int* __restrict__ c_ids, const int* __restrict__ q_ids,
    const float* __restrict__ we, const float* __restrict__ pe,
    const float* __restrict__ te,
    const float* __restrict__ g, const float* __restrict__ b,
    float* __restrict__ h, __nv_bfloat16* __restrict__ hhi,
    __nv_bfloat16* __restrict__ hlo)
{
    int row = blockIdx.x;
    const int* ids; int rlocal, S;
    if (row < CROWS) { ids = c_ids; rlocal = row;         S = CLEN; }
    else             { ids = q_ids; rlocal = row - CROWS; S = QLEN; }
    int s = rlocal % S;
    int tid = threadIdx.x;
    long long id = ids[rlocal];
    const float* w = we + id * DMODEL;
    float x[3];
    #pragma unroll
    for (int l = 0; l < 3; l++) {
        int d = tid + l * 256;
        x[l] = w[d] + pe[(size_t)s * DMODEL + d] + te[d];
    }
    float mean = block_reduce_sum(x[0] + x[1] + x[2]) * (1.f / DMODEL);
    float vs = 0.f;
    #pragma unroll
    for (int l = 0; l < 3; l++) { float dd = x[l] - mean; vs += dd * dd; }
    float rstd = rsqrtf(block_reduce_sum(vs) * (1.f / DMODEL) + 1e-12f);
    size_t base = (size_t)row * DMODEL;
    #pragma unroll
    for (int l = 0; l < 3; l++) {
        int d = tid + l * 256;
        float y = (x[l] - mean) * rstd * g[d] + b[d];
        h[base + d] = y;
        __nv_bfloat16 hi, lo; split_bf16(y, hi, lo);
        hhi[base + d] = hi; hlo[base + d] = lo;
    }
}

__global__ void __launch_bounds__(256) add_ln_kernel(
    float* __restrict__ h, const float* __restrict__ a,
    const float* __restrict__ g, const float* __restrict__ b,
    __nv_bfloat16* __restrict__ hhi, __nv_bfloat16* __restrict__ hlo)
{
    int row = blockIdx.x;
    int tid = threadIdx.x;
    size_t base = (size_t)row * DMODEL;
    float x[3];
    #pragma unroll
    for (int l = 0; l < 3; l++) {
        int d = tid + l * 256;
        x[l] = h[base + d] + a[base + d];
    }
    float mean = block_reduce_sum(x[0] + x[1] + x[2]) * (1.f / DMODEL);
    float vs = 0.f;
    #pragma unroll
    for (int l = 0; l < 3; l++) { float dd = x[l] - mean; vs += dd * dd; }
    float rstd = rsqrtf(block_reduce_sum(vs) * (1.f / DMODEL) + 1e-12f);
    #pragma unroll
    for (int l = 0; l < 3; l++) {
        int d = tid + l * 256;
        float y = (x[l] - mean) * rstd * g[d] + b[d];
        h[base + d] = y;
        __nv_bfloat16 hi, lo; split_bf16(y, hi, lo);
        hhi[base + d] = hi; hlo[base + d] = lo;
    }
}

// ---------------------------------------------------------------------------
// Split-bf16 HMMA GEMM, 4-stage cp.async pipeline, single sync per k-tile.
// ---------------------------------------------------------------------------
#define TILE_B  (128 * 40 * 2)          // 10240 bytes per tile
#define STAGE_B (4 * TILE_B)            // 40960 per stage
#define SMEMSZ  (4 * STAGE_B)           // 163840 (1 CTA/SM)

__global__ void __launch_bounds__(256) mma_gemm(
    const __nv_bfloat16* __restrict__ Ahi, const __nv_bfloat16* __restrict__ Alo,
    const __nv_bfloat16* __restrict__ Bhi, const __nv_bfloat16* __restrict__ Blo,
    const float* __restrict__ bias, const float* __restrict__ bias2,
    const float* __restrict__ bias3,
    float* __restrict__ Cf, __nv_bfloat16* __restrict__ Chi, __nv_bfloat16* __restrict__ Clo,
    int M, int N, int K, int epi)
{
    extern __shared__ char smem[];
    uint32_t sbase = smem_u32(smem);
    int tid = threadIdx.x, lane = tid & 31, wid = tid >> 5;
    int wm = wid & 3, wn = wid >> 2;
    int bm = blockIdx.y * 128, bn = blockIdx.x * 128;
    int nkt = K >> 5;

    float acc[2][8][4] = {};

    int lrow = tid >> 2;
    int lc16 = tid & 3;

    auto load_stage = [&](int buf, int kt) {
        int kb = kt * 32 + lc16 * 8;
        uint32_t dbase = sbase + buf * STAGE_B;
        #pragma unroll
        for (int c = 0; c < 2; c++) {
            int row = lrow + c * 64;
            uint32_t so = (uint32_t)(row * 80 + lc16 * 16);
            CP_ASYNC16(dbase + 0 * TILE_B + so, Ahi + (size_t)(bm + row) * K + kb);
            CP_ASYNC16(dbase + 1 * TILE_B + so, Alo + (size_t)(bm + row) * K + kb);
            CP_ASYNC16(dbase + 2 * TILE_B + so, Bhi + (size_t)(bn + row) * K + kb);
            CP_ASYNC16(dbase + 3 * TILE_B + so, Blo + (size_t)(bn + row) * K + kb);
        }
        CP_COMMIT();
    };

    load_stage(0, 0);
    load_stage(1, 1);
    load_stage(2, 2);

    for (int kt = 0; kt < nkt; kt++) {
        int rem = nkt - 1 - kt;
        if (rem >= 2)      CP_WAIT(2);
        else if (rem == 1) CP_WAIT(1);
        else               CP_WAIT(0);
        __syncthreads();

        uint32_t abase = sbase + (uint32_t)(kt & 3) * STAGE_B;
        #pragma unroll
        for (int ks = 0; ks < 2; ks++) {
            uint32_t koff = (uint32_t)((ks * 16 + (lane >> 4) * 8) * 2);
            uint32_t ah[2][4], al[2][4];
            #pragma unroll
            for (int mt = 0; mt < 2; mt++) {
                uint32_t r = abase + (uint32_t)((wm * 32 + mt * 16 + (lane & 15)) * 80) + koff;
                ldsm_x4(ah[mt], r);
                ldsm_x4(al[mt], r + TILE_B);
            }
            uint32_t bh[2][4], bl[2][4];
            {
                uint32_t r = abase + 2 * TILE_B
                           + (uint32_t)((wn * 64 + (lane & 15)) * 80) + koff;
                ldsm_x4(bh[0], r);
                ldsm_x4(bl[0], r + TILE_B);
            }
            #pragma unroll
            for (int nt = 0; nt < 4; nt++) {
                int c = nt & 1;
                if (nt < 3) {
                    uint32_t r = abase + 2 * TILE_B
                               + (uint32_t)((wn * 64 + (nt + 1) * 16 + (lane & 15)) * 80) + koff;
                    ldsm_x4(bh[c ^ 1], r);
                    ldsm_x4(bl[c ^ 1], r + TILE_B);
                }
                #pragma unroll
                for (int mt = 0; mt < 2; mt++) {
                    mma_bf16(acc[mt][nt * 2 + 0], ah[mt], bh[c][0], bh[c][2]);
                    mma_bf16(acc[mt][nt * 2 + 0], ah[mt], bl[c][0], bl[c][2]);
                    mma_bf16(acc[mt][nt * 2 + 0], al[mt], bh[c][0], bh[c][2]);
                    mma_bf16(acc[mt][nt * 2 + 1], ah[mt], bh[c][1], bh[c][3]);
                    mma_bf16(acc[mt][nt * 2 + 1], ah[mt], bl[c][1], bl[c][3]);
                    mma_bf16(acc[mt][nt * 2 + 1], al[mt], bh[c][1], bh[c][3]);
                }
            }
        }
        if (kt + 3 < nkt) load_stage((kt + 3) & 3, kt + 3);
    }

    int g = lane >> 2, t4 = lane & 3;
    #pragma unroll
    for (int mt = 0; mt < 2; mt++) {
        #pragma unroll
        for (int nt = 0; nt < 4; nt++) {
            #pragma unroll
            for (int h8 = 0; h8 < 2; h8++) {
                float* d = acc[mt][nt * 2 + h8];
                int c0 = bn + wn * 64 + nt * 16 + h8 * 8 + t4 * 2;
                #pragma unroll
                for (int rr = 0; rr < 2; rr++) {
                    int r = bm + wm * 32 + mt * 16 + g + rr * 8;
                    float v0 = d[rr * 2 + 0], v1 = d[rr * 2 + 1];
                    if (epi == 3) {
                        if (c0 < DMODEL) {
                            v0 = (v0 + __ldg(bias + c0)) * 0.125f;
                            v1 = (v1 + __ldg(bias + c0 + 1)) * 0.125f;
                        } else if (c0 < 2 * DMODEL) {
                            v0 += __ldg(bias2 + c0 - DMODEL);
                            v1 += __ldg(bias2 + c0 + 1 - DMODEL);
                        } else {
                            v0 += __ldg(bias3 + c0 - 2 * DMODEL);
                            v1 += __ldg(bias3 + c0 + 1 - 2 * DMODEL);
                        }
                    } else if (bias) {
                        v0 += __ldg(bias + c0);
                        v1 += __ldg(bias + c0 + 1);
                    }
                    if (epi == 2) {
                        v0 = 0.5f * v0 * (1.f + erff(v0 * 0.7071067811865476f));
                        v1 = 0.5f * v1 * (1.f + erff(v1 * 0.7071067811865476f));
                        __nv_bfloat16 h0, l0, h1, l1;
                        split_bf16(v0, h0, l0); split_bf16(v1, h1, l1);
                        size_t idx = (size_t)r * N + c0;
                        *(__nv_bfloat162*)&Chi[idx] = __nv_bfloat162(h0, h1);
                        *(__nv_bfloat162*)&Clo[idx] = __nv_bfloat162(l0, l1);
                        continue;
                    }
                    float2 o; o.x = v0; o.y = v1;
                    *(float2*)&Cf[(size_t)r * N + c0] = o;
                }
            }
        }
    }
}

// ---------------------------------------------------------------------------
// Sliding-window attention v6: mma flash attention; V staged row-major and
// consumed via ldmatrix.trans (no scalar transpose stores).
// ---------------------------------------------------------------------------
#define AKOFF_LO 4608
#define AVOFF    9216
#define AVOFF_LO 13824
#define AQOFF_LO 9216

__global__ void __launch_bounds__(128, 3) local_attn_kernel(
    const float* __restrict__ QKV, const int* __restrict__ mask,
    __nv_bfloat16* __restrict__ Ohi, __nv_bfloat16* __restrict__ Olo,
    int nc, int S, int row_base)
{
    __shared__ char  sbuf[18432];
    __shared__ float sbias[3 * CHUNK];
    __shared__ int   skpos[3 * CHUNK];

    int nb = blockIdx.x;
    int n = nb >> 2, qt = nb & 3;
    int h = blockIdx.y, b = blockIdx.z;
    int tid = threadIdx.x;
    int lane = tid & 31, w = tid >> 5;
    int g = lane >> 2, t4 = lane & 3;
    uint32_t sb32 = smem_u32(sbuf);

    #pragma unroll
    for (int jj = 0; jj < 6; jj++) {
        int j = tid + jj * 128;
        int cn = n - 1 + (j >> 8);
        bool cv = (cn >= 0) && (cn < nc);
        int cnc = min(max(cn, 0), nc - 1);
        int kpos = cnc * CHUNK + (j & 255);
        sbias[j] = (cv && mask[b * S + kpos] != 0) ? 0.f : -1e30f;
        skpos[j] = kpos;
    }

    // stage Q: 64 rows x 64 dims, hi/lo, 144B pitch
    {
        int row = tid >> 1, half = tid & 1;
        const float* src = QKV + (size_t)(row_base + b * S + n * CHUNK + qt * 64 + row) * NQKV
                         + h * DHEAD + half * 32;
        float f[32];
        #pragma unroll
        for (int e = 0; e < 8; e++) {
            float4 t = *(const float4*)(src + e * 4);
            f[e*4+0] = t.x; f[e*4+1] = t.y; f[e*4+2] = t.z; f[e*4+3] = t.w;
        }
        uint32_t hi[16], lo[16];
        #pragma unroll
        for (int e = 0; e < 16; e++) split_pack2(f[2*e], f[2*e+1], hi[e], lo[e]);
        char* dst = sbuf + row * 144 + half * 64;
        #pragma unroll
        for (int e = 0; e < 4; e++) {
            *(uint4*)(dst + e * 16) = make_uint4(hi[e*4], hi[e*4+1], hi[e*4+2], hi[e*4+3]);
            *(uint4*)(dst + AQOFF_LO + e * 16) = make_uint4(lo[e*4], lo[e*4+1], lo[e*4+2], lo[e*4+3]);
        }
    }
    __syncthreads();

    uint32_t qh[4][4], ql[4][4];
    #pragma unroll
    for (int kc = 0; kc < 4; kc++) {
        uint32_t addr = sb32 + (uint32_t)((w * 16 + (lane & 15)) * 144 + kc * 32 + (lane >> 4) * 16);
        ldsm_x4(qh[kc], addr);
        ldsm_x4(ql[kc], addr + AQOFF_LO);
    }

    float m0 = -1e30f, m1 = -1e30f, l0 = 0.f, l1 = 0.f;
    float O[8][4] = {};

    int jlo = (n == 0) ? CHUNK : 0;
    int jhi = (n == nc - 1) ? (2 * CHUNK - 1) : (3 * CHUNK - 1);
    int wq0 = qt * 64 + w * 16;
    int wjs = max(wq0, jlo), wje = min(wq0 + 15 + WINW, jhi);
    int bjs = max(qt * 64, jlo), bje = min(qt * 64 + 63 + WINW, jhi);
    int iq0 = wq0 + g, iq1 = iq0 + 8;

    const float* kvb = QKV + (size_t)(row_base + b * S) * NQKV + DMODEL + h * DHEAD;

    for (int t0 = bjs & ~31; t0 <= bje; t0 += 32) {
        __syncthreads();
        // stage K and V, both [32 keys x 64 dims] hi/lo, 144B pitch
        {
            int key = tid >> 2, dg = tid & 3;
            int j = min(t0 + key, 3 * CHUNK - 1);
            const float* src = kvb + (size_t)skpos[j] * NQKV + dg * 16;
            float f[16];
            #pragma unroll
            for (int e = 0; e < 4; e++) {
                float4 t = *(const float4*)(src + e * 4);
                f[e*4+0] = t.x; f[e*4+1] = t.y; f[e*4+2] = t.z; f[e*4+3] = t.w;
            }
            uint32_t hi[8], lo[8];
            #pragma unroll
            for (int e = 0; e < 8; e++) split_pack2(f[2*e], f[2*e+1], hi[e], lo[e]);
            char* kdst = sbuf + key * 144 + dg * 32;
            *(uint4*)(kdst)                 = make_uint4(hi[0], hi[1], hi[2], hi[3]);
            *(uint4*)(kdst + 16)            = make_uint4(hi[4], hi[5], hi[6], hi[7]);
            *(uint4*)(kdst + AKOFF_LO)      = make_uint4(lo[0], lo[1], lo[2], lo[3]);
            *(uint4*)(kdst + AKOFF_LO + 16) = make_uint4(lo[4], lo[5], lo[6], lo[7]);
            const float* vsrc = src + DMODEL;
            #pragma unroll
            for (int e = 0; e < 4; e++) {
                float4 t = *(const float4*)(vsrc + e * 4);
                f[e*4+0] = t.x; f[e*4+1] = t.y; f[e*4+2] = t.z; f[e*4+3] = t.w;
            }
            #pragma unroll
            for (int e = 0; e < 8; e++) split_pack2(f[2*e], f[2*e+1], hi[e], lo[e]);
            char* vdst = sbuf + AVOFF + key * 144 + dg * 32;
            *(uint4*)(vdst)               = make_uint4(hi[0], hi[1], hi[2], hi[3]);
            *(uint4*)(vdst + 16)          = make_uint4(hi[4], hi[5], hi[6], hi[7]);
            *(uint4*)(vdst + 4608)        = make_uint4(lo[0], lo[1], lo[2], lo[3]);
            *(uint4*)(vdst + 4608 + 16)   = make_uint4(lo[4], lo[5], lo[6], lo[7]);
        }
        __syncthreads();

        if (t0 + 31 < wjs || t0 > wje) continue;

        // --- scores S[16 x 32] ---
        float Sc[4][4];
        #pragma unroll
        for (int tt = 0; tt < 4; tt++)
            #pragma unroll
            for (int e = 0; e < 4; e++) Sc[tt][e] = 0.f;

        #pragma unroll
        for (int kc = 0; kc < 4; kc++) {
            #pragma unroll
            for (int kh = 0; kh < 2; kh++) {
                uint32_t bh[4], bl[4];
                uint32_t addr = sb32 + (uint32_t)((kh * 16 + (lane & 15)) * 144 + kc * 32 + (lane >> 4) * 16);
                ldsm_x4(bh, addr);
                ldsm_x4(bl, addr + AKOFF_LO);
                int t = kh * 2;
                mma_bf16(Sc[t],     qh[kc], bh[0], bh[2]);
                mma_bf16(Sc[t],     qh[kc], bl[0], bl[2]);
                mma_bf16(Sc[t],     ql[kc], bh[0], bh[2]);
                mma_bf16(Sc[t + 1], qh[kc], bh[1], bh[3]);
                mma_bf16(Sc[t + 1], qh[kc], bl[1], bl[3]);
                mma_bf16(Sc[t + 1], ql[kc], bh[1], bh[3]);
            }
        }

        // --- mask + row max ---
        float rm0 = -1e30f, rm1 = -1e30f;
        #pragma unroll
        for (int tt = 0; tt < 4; tt++) {
            int j0 = t0 + tt * 8 + 2 * t4, j1 = j0 + 1;
            float sb0 = sbias[min(j0, 3 * CHUNK - 1)];
            float sb1 = sbias[min(j1, 3 * CHUNK - 1)];
            bool v00 = (sb0 == 0.f) && (j0 >= iq0) && (j0 <= iq0 + WINW);
            bool v01 = (sb1 == 0.f) && (j1 >= iq0) && (j1 <= iq0 + WINW);
            bool v10 = (sb0 == 0.f) && (j0 >= iq1) && (j0 <= iq1 + WINW);
            bool v11 = (sb1 == 0.f) && (j1 >= iq1) && (j1 <= iq1 + WINW);
            Sc[tt][0] = v00 ? Sc[tt][0] : -1e30f;
            Sc[tt][1] = v01 ? Sc[tt][1] : -1e30f;
            Sc[tt][2] = v10 ? Sc[tt][2] : -1e30f;
            Sc[tt][3] = v11 ? Sc[tt][3] : -1e30f;
            rm0 = fmaxf(rm0, fmaxf(Sc[tt][0], Sc[tt][1]));
            rm1 = fmaxf(rm1, fmaxf(Sc[tt][2], Sc[tt][3]));
        }
        rm0 = fmaxf(rm0, __shfl_xor_sync(0xffffffffu, rm0, 1));
        rm0 = fmaxf(rm0, __shfl_xor_sync(0xffffffffu, rm0, 2));
        rm1 = fmaxf(rm1, __shfl_xor_sync(0xffffffffu, rm1, 1));
        rm1 = fmaxf(rm1, __shfl_xor_sync(0xffffffffu, rm1, 2));

        float mn0 = fmaxf(m0, rm0), mn1 = fmaxf(m1, rm1);
        float c0 = __expf(m0 - mn0), c1 = __expf(m1 - mn1);
        l0 *= c0; l1 *= c1;
        #pragma unroll
        for (int dt = 0; dt < 8; dt++) {
            O[dt][0] *= c0; O[dt][1] *= c0;
            O[dt][2] *= c1; O[dt][3] *= c1;
        }
        m0 = mn0; m1 = mn1;

        float rs0 = 0.f, rs1 = 0.f;
        #pragma unroll
        for (int tt = 0; tt < 4; tt++) {
            float p0 = (Sc[tt][0] > -5e29f) ? __expf(Sc[tt][0] - m0) : 0.f;
            float p1 = (Sc[tt][1] > -5e29f) ? __expf(Sc[tt][1] - m0) : 0.f;
            float p2 = (Sc[tt][2] > -5e29f) ? __expf(Sc[tt][2] - m1) : 0.f;
            float p3 = (Sc[tt][3] > -5e29f) ? __expf(Sc[tt][3] - m1) : 0.f;
            Sc[tt][0] = p0; Sc[tt][1] = p1; Sc[tt][2] = p2; Sc[tt][3] = p3;
            rs0 += p0 + p1; rs1 += p2 + p3;
        }
        rs0 += __shfl_xor_sync(0xffffffffu, rs0, 1);
        rs0 += __shfl_xor_sync(0xffffffffu, rs0, 2);
        rs1 += __shfl_xor_sync(0xffffffffu, rs1, 1);
        rs1 += __shfl_xor_sync(0xffffffffu, rs1, 2);
        l0 += rs0; l1 += rs1;

        // --- P @ V via trans-ldsm B fragments ---
        #pragma unroll
        for (int kc2 = 0; kc2 < 2; kc2++) {
            int ta = kc2 * 2, tb = ta + 1;
            uint32_t ah[4], al[4];
            split_pack2(Sc[ta][0], Sc[ta][1], ah[0], al[0]);
            split_pack2(Sc[ta][2], Sc[ta][3], ah[1], al[1]);
            split_pack2(Sc[tb][0], Sc[tb][1], ah[2], al[2]);
            split_pack2(Sc[tb][2], Sc[tb][3], ah[3], al[3]);
            uint32_t vrow = (uint32_t)(kc2 * 16 + (lane & 7) + ((lane & 16) ? 8 : 0));
            #pragma unroll
            for (int dt = 0; dt < 4; dt++) {
                uint32_t bh[4], bl[4];
                uint32_t addr = sb32 + AVOFF + vrow * 144
                              + (uint32_t)(dt * 32 + ((lane & 8) ? 16 : 0));
                ldsm_x4_trans(bh, addr);
                ldsm_x4_trans(bl, addr + 4608);
                mma_bf16(O[dt * 2],     ah, bh[0], bh[2]);
                mma_bf16(O[dt * 2],     ah, bl[0], bl[2]);
                mma_bf16(O[dt * 2],     al, bh[0], bh[2]);
                mma_bf16(O[dt * 2 + 1], ah, bh[1], bh[3]);
                mma_bf16(O[dt * 2 + 1], ah, bl[1], bl[3]);
                mma_bf16(O[dt * 2 + 1], al, bh[1], bh[3]);
            }
        }
    }

    float inv0 = 1.f / l0, inv1 = 1.f / l1;
    int qrow0 = row_base + b * S + n * CHUNK + wq0 + g;
    #pragma unroll
    for (int dt = 0; dt < 8; dt++) {
        int col = h * DHEAD + dt * 8 + 2 * t4;
        size_t i0 = (size_t)qrow0 * DMODEL + col;
        size_t i1 = i0 + (size_t)8 * DMODEL;
        float a0 = O[dt][0] * inv0, a1 = O[dt][1] * inv0;
        float b0 = O[dt][2] * inv1, b1 = O[dt][3] * inv1;
        __nv_bfloat16 h0, lo0, h1, lo1;
        split_bf16(a0, h0, lo0); split_bf16(a1, h1, lo1);
        *(__nv_bfloat162*)&Ohi[i0] = __nv_bfloat162(h0, h1);
        *(__nv_bfloat162*)&Olo[i0] = __nv_bfloat162(lo0, lo1);
        split_bf16(b0, h0, lo0); split_bf16(b1, h1, lo1);
        *(__nv_bfloat162*)&Ohi[i1] = __nv_bfloat162(h0, h1);
        *(__nv_bfloat162*)&Olo[i1] = __nv_bfloat162(lo0, lo1);
    }
}

// ---------------------------------------------------------------------------
// Interaction head
// ---------------------------------------------------------------------------
__global__ void init_re_kernel(float* __restrict__ re)
{
    re[blockIdx.x * 256 + threadIdx.x] = 0.f;
}

__global__ void __launch_bounds__(256) softmax_max_kernel(
    const float* __restrict__ P, float* __restrict__ re)
{
    int row = blockIdx.x, tid = threadIdx.x;
    int b = row / CLEN;
    const float* p = P + (size_t)row * QLEN;
    float x0 = p[tid], x1 = p[tid + 256];
    float m = block_reduce_max(fmaxf(x0, x1));
    float e0 = __expf(x0 - m), e1 = __expf(x1 - m);
    float s = block_reduce_sum(e0 + e1);
    float inv = 1.f / s;
    unsigned* r = (unsigned*)(re + b * QLEN);
    atomicMax(r + tid,       __float_as_uint(e0 * inv));
    atomicMax(r + tid + 256, __float_as_uint(e1 * inv));
}

__global__ void fc_kernel(const float* __restrict__ re, const float* __restrict__ w,
                          const float* __restrict__ bfc, float* __restrict__ out)
{
    int t = threadIdx.x;
    if (t >= 8) return;
    int b = t >> 2, o = t & 3;
    float s = bfc[o];
    for (int q = 0; q < QLEN; q++) s += re[b * QLEN + q] * w[q * 4 + o];
    out[b * 4 + o] = s;
}

// ---------------------------------------------------------------------------
// Host orchestration
// ---------------------------------------------------------------------------
extern "C" void kernel_launch(void* const* d_in, const int* in_sizes, int n_in,
                              void* d_out, int out_size)
{
    const int*   q_ids    = (const int*)  d_in[0];
    const int*   c_ids    = (const int*)  d_in[1];
    const int*   q_mask   = (const int*)  d_in[2];
    const int*   c_mask   = (const int*)  d_in[3];
    const float* word_emb = (const float*)d_in[4];
    const float* pos_emb  = (const float*)d_in[5];
    const float* type_emb = (const float*)d_in[6];
    const float* eg       = (const float*)d_in[7];
    const float* eb       = (const float*)d_in[8];
    const float* Wq  = (const float*)d_in[9];
    const float* bq  = (const float*)d_in[10];
    const float* Wk  = (const float*)d_in[11];
    const float* bk  = (const float*)d_in[12];
    const float* Wv  = (const float*)d_in[13];
    const float* bv  = (const float*)d_in[14];
    const float* Wo  = (const float*)d_in[15];
    const float* bo  = (const float*)d_in[16];
    const float* l1g = (const float*)d_in[17];
    const float* l1b = (const float*)d_in[18];
    const float* W1  = (const float*)d_in[19];
    const float* b1  = (const float*)d_in[20];
    const float* W2  = (const float*)d_in[21];
    const float* b2  = (const float*)d_in[22];
    const float* l2g = (const float*)d_in[23];
    const float* l2b = (const float*)d_in[24];
    const float* fcw = (const float*)d_in[25];
    const float* fcb = (const float*)d_in[26];

    cudaFuncSetAttribute(mma_gemm, cudaFuncAttributeMaxDynamicSharedMemorySize, SMEMSZ);

    __nv_bfloat16 *wqkvhi, *wqkvlo, *wohi, *wolo, *w1hi, *w1lo, *w2hi, *w2lo;
    __nv_bfloat16 *hhi, *hlo, *sthi, *stlo, *ffnhi, *ffnlo;
    float *h, *qkv, *t2, *ssc, *sre;
    cudaGetSymbolAddress((void**)&wqkvhi, g_wqkv_hi);
    cudaGetSymbolAddress((void**)&wqkvlo, g_wqkv_lo);
    cudaGetSymbolAddress((void**)&wohi,   g_wo_hi);
    cudaGetSymbolAddress((void**)&wolo,   g_wo_lo);
    cudaGetSymbolAddress((void**)&w1hi,   g_w1_hi);
    cudaGetSymbolAddress((void**)&w1lo,   g_w1_lo);
    cudaGetSymbolAddress((void**)&w2hi,   g_w2_hi);
    cudaGetSymbolAddress((void**)&w2lo,   g_w2_lo);
    cudaGetSymbolAddress((void**)&h,      g_h);
    cudaGetSymbolAddress((void**)&hhi,    g_h_hi);
    cudaGetSymbolAddress((void**)&hlo,    g_h_lo);
    cudaGetSymbolAddress((void**)&qkv,    g_qkv);
    cudaGetSymbolAddress((void**)&t2,     g_t2);
    cudaGetSymbolAddress((void**)&sthi,   g_st_hi);
    cudaGetSymbolAddress((void**)&stlo,   g_st_lo);
    cudaGetSymbolAddress((void**)&ffnhi,  g_ffn_hi);
    cudaGetSymbolAddress((void**)&ffnlo,  g_ffn_lo);
    cudaGetSymbolAddress((void**)&ssc,    g_sc);
    cudaGetSymbolAddress((void**)&sre,    g_re);

    dim3 gQKV(NQKV/128,   ROWSA/128);
    dim3 gD  (DMODEL/128, ROWSA/128);
    dim3 gF  (FFDIM/128,  ROWSA/128);
    dim3 gAc(4*CLEN/CHUNK, NHEAD, BATCH);
    dim3 gAq(4*QLEN/CHUNK, NHEAD, BATCH);

    // 0: QKV weight prep
    wprep_qkv_all<<<dim3(24, 24, 36), 256>>>(Wq, Wk, Wv, wqkvhi, wqkvlo);
    // 1: merged embedding
    embed_ln_all<<<ROWSA, 256>>>(c_ids, q_ids, word_emb, pos_emb, type_emb,
                                 eg, eb, h, hhi, hlo);
    // 2: Wo prep (filler so idx 3 = GEMM for the profiler)
    wprep_b<<<dim3(24, 24, NL), 256>>>(Wo, wohi, wolo, DMODEL, DMODEL);
    // 3: layer-0 merged QKV GEMM (profiling target)
    mma_gemm<<<gQKV, 256, SMEMSZ>>>(hhi, hlo, wqkvhi, wqkvlo,
        bq, bk, bv, qkv, nullptr, nullptr, ROWSA, NQKV, DMODEL, 3);
    // 4-5: layer-0 attention
    local_attn_kernel<<<gAc, 128>>>(qkv, c_mask, sthi, stlo, CLEN/CHUNK, CLEN, 0);
    local_attn_kernel<<<gAq, 128>>>(qkv, q_mask, sthi, stlo, QLEN/CHUNK, QLEN, QBASE);
    // 6-7: remaining weight prep
    wprep_b<<<dim3(96, 24, NL), 256>>>(W1, w1hi, w1lo, DMODEL, FFDIM);
    wprep_b<<<dim3(24, 96, NL), 256>>>(W2, w2hi, w2lo, FFDIM, DMODEL);

    for (int l = 0; l < NL; l++) {
        if (l > 0) {
            size_t qb = (size_t)l * QKVW;
            mma_gemm<<<gQKV, 256, SMEMSZ>>>(hhi, hlo, wqkvhi + qb, wqkvlo + qb,
                bq + l*DMODEL, bk + l*DMODEL, bv + l*DMODEL,
                qkv, nullptr, nullptr, ROWSA, NQKV, DMODEL, 3);
            local_attn_kernel<<<gAc, 128>>>(qkv, c_mask, sthi, stlo, CLEN/CHUNK, CLEN, 0);
            local_attn_kernel<<<gAq, 128>>>(qkv, q_mask, sthi, stlo, QLEN/CHUNK, QLEN, QBASE);
        }
        mma_gemm<<<gD, 256, SMEMSZ>>>(sthi, stlo, wohi + l*D2, wolo + l*D2,
            bo + l*DMODEL, nullptr, nullptr, t2, nullptr, nullptr,
            ROWSA, DMODEL, DMODEL, 0);
        add_ln_kernel<<<ROWSA, 256>>>(h, t2, l1g + l*DMODEL, l1b + l*DMODEL, hhi, hlo);
        mma_gemm<<<gF, 256, SMEMSZ>>>(hhi, hlo, w1hi + l*DF, w1lo + l*DF,
            b1 + l*FFDIM, nullptr, nullptr, nullptr, ffnhi, ffnlo,
            ROWSA, FFDIM, DMODEL, 2);
        mma_gemm<<<gD, 256, SMEMSZ>>>(ffnhi, ffnlo, w2hi + l*DF, w2lo + l*DF,
            b2 + l*DMODEL, nullptr, nullptr, t2, nullptr, nullptr,
            ROWSA, DMODEL, FFDIM, 0);
        add_ln_kernel<<<ROWSA, 256>>>(h, t2, l2g + l*DMODEL, l2b + l*DMODEL, hhi, hlo);
    }

    // interaction
    for (int b = 0; b < BATCH; b++) {
        mma_gemm<<<dim3(QLEN/128, CLEN/128), 256, SMEMSZ>>>(
            hhi + (size_t)b*CLEN*DMODEL, hlo + (size_t)b*CLEN*DMODEL,
            hhi + (size_t)(QBASE + b*QLEN)*DMODEL, hlo + (size_t)(QBASE + b*QLEN)*DMODEL,
            nullptr, nullptr, nullptr,
            ssc + (size_t)b*CLEN*QLEN, nullptr, nullptr,
            CLEN, QLEN, DMODEL, 0);
    }
    init_re_kernel<<<BATCH * QLEN / 256, 256>>>(sre);
    softmax_max_kernel<<<BATCH * CLEN, 256>>>(ssc, sre);
    fc_kernel<<<1, 32>>>(sre, fcw, fcb, (float*)d_out);
}

// round 13
// speedup vs baseline: 1.1108x; 1.1108x over previous
#include <cuda_runtime.h>
#include <cuda_bf16.h>
#include <math.h>
#include <stdint.h>

// ---------------------------------------------------------------------------
// Problem constants
// ---------------------------------------------------------------------------
#define NL     12
#define DMODEL 768
#define NHEAD  12
#define DHEAD  64
#define FFDIM  3072
#define BATCH  2
#define QLEN   512
#define CLEN   2048
#define CHUNK  256
#define WINW   512
#define NQKV   2304
#define CROWS  (BATCH * CLEN)
#define QROWS  (BATCH * QLEN)
#define ROWSA  (CROWS + QROWS)
#define QBASE  CROWS

// ---------------------------------------------------------------------------
// PTX helpers
// ---------------------------------------------------------------------------
__device__ __forceinline__ uint32_t smem_u32(const void* p) {
    uint32_t a;
    asm("{ .reg .u64 t; cvta.to.shared.u64 t, %1; cvt.u32.u64 %0, t; }" : "=r"(a) : "l"(p));
    return a;
}
__device__ __forceinline__ void ldsm_x4(uint32_t* r, uint32_t addr) {
    asm volatile("ldmatrix.sync.aligned.m8n8.x4.shared.b16 {%0,%1,%2,%3}, [%4];"
                 : "=r"(r[0]), "=r"(r[1]), "=r"(r[2]), "=r"(r[3]) : "r"(addr));
}
__device__ __forceinline__ void ldsm_x4_trans(uint32_t* r, uint32_t addr) {
    asm volatile("ldmatrix.sync.aligned.m8n8.x4.trans.shared.b16 {%0,%1,%2,%3}, [%4];"
                 : "=r"(r[0]), "=r"(r[1]), "=r"(r[2]), "=r"(r[3]) : "r"(addr));
}
__device__ __forceinline__ void mma_bf16(float* c, const uint32_t* a, uint32_t b0, uint32_t b1) {
    asm volatile(
        "mma.sync.aligned.m16n8k16.row.col.f32.bf16.bf16.f32 "
        "{%0,%1,%2,%3}, {%4,%5,%6,%7}, {%8,%9}, {%0,%1,%2,%3};"
        : "+f"(c[0]), "+f"(c[1]), "+f"(c[2]), "+f"(c[3])
        : "r"(a[0]), "r"(a[1]), "r"(a[2]), "r"(a[3]), "r"(b0), "r"(b1));
}
#define CP_ASYNC16(dst, src) \
    asm volatile("cp.async.cg.shared.global [%0], [%1], 16;" :: "r"(dst), "l"(src))
#define CP_COMMIT() asm volatile("cp.async.commit_group;")
#define CP_WAIT(n)  asm volatile("cp.async.wait_group %0;" :: "n"(n))

// ---------------------------------------------------------------------------
// Scratch (device globals)
// ---------------------------------------------------------------------------
#define D2   ((size_t)DMODEL * DMODEL)
#define DF   ((size_t)DMODEL * FFDIM)
#define QKVW (3ull * D2)

__device__ __nv_bfloat16 g_wqkv_hi[12 * QKVW];
__device__ __nv_bfloat16 g_wqkv_lo[12 * QKVW];
__device__ __nv_bfloat16 g_wo_hi[12 * D2];
__device__ __nv_bfloat16 g_wo_lo[12 * D2];
__device__ __nv_bfloat16 g_w1_hi[12 * DF];
__device__ __nv_bfloat16 g_w1_lo[12 * DF];
__device__ __nv_bfloat16 g_w2_hi[12 * DF];
__device__ __nv_bfloat16 g_w2_lo[12 * DF];

__device__ float g_h [ROWSA * DMODEL];
__device__ __nv_bfloat16 g_h_hi[ROWSA * DMODEL];
__device__ __nv_bfloat16 g_h_lo[ROWSA * DMODEL];
__device__ float g_qkv[ROWSA * NQKV];
__device__ float g_t2 [ROWSA * DMODEL];
__device__ __nv_bfloat16 g_st_hi[ROWSA * DMODEL];
__device__ __nv_bfloat16 g_st_lo[ROWSA * DMODEL];
__device__ __nv_bfloat16 g_ffn_hi[ROWSA * FFDIM];
__device__ __nv_bfloat16 g_ffn_lo[ROWSA * FFDIM];

__device__ float g_sc [BATCH * CLEN * QLEN];
__device__ float g_re [BATCH * QLEN];

// ---------------------------------------------------------------------------
// Reductions
// ---------------------------------------------------------------------------
__device__ __forceinline__ float block_reduce_sum(float v) {
    __shared__ float sh[33];
    int lane = threadIdx.x & 31, wid = threadIdx.x >> 5;
    #pragma unroll
    for (int o = 16; o; o >>= 1) v += __shfl_xor_sync(0xffffffffu, v, o);
    if (lane == 0) sh[wid] = v;
    __syncthreads();
    if (wid == 0) {
        float t = (lane < 8) ? sh[lane] : 0.f;
        #pragma unroll
        for (int o = 4; o; o >>= 1) t += __shfl_xor_sync(0xffffffffu, t, o);
        if (lane == 0) sh[32] = t;
    }
    __syncthreads();
    float r = sh[32];
    __syncthreads();
    return r;
}
__device__ __forceinline__ float block_reduce_max(float v) {
    __shared__ float sh[33];
    int lane = threadIdx.x & 31, wid = threadIdx.x >> 5;
    #pragma unroll
    for (int o = 16; o; o >>= 1) v = fmaxf(v, __shfl_xor_sync(0xffffffffu, v, o));
    if (lane == 0) sh[wid] = v;
    __syncthreads();
    if (wid == 0) {
        float t = (lane < 8) ? sh[lane] : -1e30f;
        #pragma unroll
        for (int o = 4; o; o >>= 1) t = fmaxf(t, __shfl_xor_sync(0xffffffffu, t, o));
        if (lane == 0) sh[32] = t;
    }
    __syncthreads();
    float r = sh[32];
    __syncthreads();
    return r;
}

__device__ __forceinline__ void split_bf16(float x, __nv_bfloat16& hi, __nv_bfloat16& lo) {
    hi = __float2bfloat16(x);
    lo = __float2bfloat16(x - __bfloat162float(hi));
}
__device__ __forceinline__ void split_pack2(float a, float b, uint32_t& hi, uint32_t& lo) {
    __nv_bfloat16 ah, al, bh, bl;
    split_bf16(a, ah, al); split_bf16(b, bh, bl);
    __nv_bfloat162 H(ah, bh), L(al, bl);
    hi = *(uint32_t*)&H; lo = *(uint32_t*)&L;
}

// ---------------------------------------------------------------------------
// Batched weight transpose + split
// ---------------------------------------------------------------------------
__global__ void __launch_bounds__(256) wprep_qkv_all(
    const float* __restrict__ Wq, const float* __restrict__ Wk,
    const float* __restrict__ Wv,
    __nv_bfloat16* __restrict__ Thi, __nv_bfloat16* __restrict__ Tlo)
{
    __shared__ float t[32][33];
    int z = blockIdx.z;
    int l = z / 3, which = z % 3;
    const float* W = (which == 0 ? Wq : (which == 1 ? Wk : Wv)) + (size_t)l * D2;
    __nv_bfloat16* ohi = Thi + (size_t)l * QKVW + (size_t)which * D2;
    __nv_bfloat16* olo = Tlo + (size_t)l * QKVW + (size_t)which * D2;
    int tx = threadIdx.x & 31, ty = threadIdx.x >> 5;
    int n0 = blockIdx.x * 32, k0 = blockIdx.y * 32;
    #pragma unroll
    for (int j = 0; j < 4; j++)
        t[ty + 8 * j][tx] = W[(size_t)(k0 + ty + 8 * j) * DMODEL + n0 + tx];
    __syncthreads();
    #pragma unroll
    for (int j = 0; j < 4; j++) {
        int n = n0 + ty + 8 * j, k = k0 + tx;
        __nv_bfloat16 hi, lo;
        split_bf16(t[tx][ty + 8 * j], hi, lo);
        ohi[(size_t)n * DMODEL + k] = hi;
        olo[(size_t)n * DMODEL + k] = lo;
    }
}

__global__ void __launch_bounds__(256) wprep_b(
    const float* __restrict__ W, __nv_bfloat16* __restrict__ Thi,
    __nv_bfloat16* __restrict__ Tlo, int K, int N)
{
    __shared__ float t[32][33];
    size_t l = blockIdx.z;
    const float* Wl = W + l * (size_t)K * N;
    __nv_bfloat16* ohi = Thi + l * (size_t)K * N;
    __nv_bfloat16* olo = Tlo + l * (size_t)K * N;
    int tx = threadIdx.x & 31, ty = threadIdx.x >> 5;
    int n0 = blockIdx.x * 32, k0 = blockIdx.y * 32;
    #pragma unroll
    for (int j = 0; j < 4; j++)
        t[ty + 8 * j][tx] = Wl[(size_t)(k0 + ty + 8 * j) * N + n0 + tx];
    __syncthreads();
    #pragma unroll
    for (int j = 0; j < 4; j++) {
        int n = n0 + ty + 8 * j, k = k0 + tx;
        __nv_bfloat16 hi, lo;
        split_bf16(t[tx][ty + 8 * j], hi, lo);
        ohi[(size_t)n * K + k] = hi;
        olo[(size_t)n * K + k] = lo;
    }
}

// ---------------------------------------------------------------------------
// Merged embedding + LN / Add + LN
// ---------------------------------------------------------------------------
__global__ void __launch_bounds__(256) embed_ln_all(
    const int* __restrict__ c_ids, const int* __restrict__ q_ids,
    const float* __restrict__ we, const float* __restrict__ pe,
    const float* __restrict__ te,
    const float* __restrict__ g, const float* __restrict__ b,
    float* __restrict__ h, __nv_bfloat16* __restrict__ hhi,
    __nv_bfloat16* __restrict__ hlo)
{
    int row = blockIdx.x;
    const int* ids; int rlocal, S;
    if (row < CROWS) { ids = c_ids; rlocal = row;         S = CLEN; }
    else             { ids = q_ids; rlocal = row - CROWS; S = QLEN; }
    int s = rlocal % S;
    int tid = threadIdx.x;
    long long id = ids[rlocal];
    const float* w = we + id * DMODEL;
    float x[3];
    #pragma unroll
    for (int l = 0; l < 3; l++) {
        int d = tid + l * 256;
        x[l] = w[d] + pe[(size_t)s * DMODEL + d] + te[d];
    }
    float mean = block_reduce_sum(x[0] + x[1] + x[2]) * (1.f / DMODEL);
    float vs = 0.f;
    #pragma unroll
    for (int l = 0; l < 3; l++) { float dd = x[l] - mean; vs += dd * dd; }
    float rstd = rsqrtf(block_reduce_sum(vs) * (1.f / DMODEL) + 1e-12f);
    size_t base = (size_t)row * DMODEL;
    #pragma unroll
    for (int l = 0; l < 3; l++) {
        int d = tid + l * 256;
        float y = (x[l] - mean) * rstd * g[d] + b[d];
        h[base + d] = y;
        __nv_bfloat16 hi, lo; split_bf16(y, hi, lo);
        hhi[base + d] = hi; hlo[base + d] = lo;
    }
}

__global__ void __launch_bounds__(256) add_ln_kernel(
    float* __restrict__ h, const float* __restrict__ a,
    const float* __restrict__ g, const float* __restrict__ b,
    __nv_bfloat16* __restrict__ hhi, __nv_bfloat16* __restrict__ hlo)
{
    int row = blockIdx.x;
    int tid = threadIdx.x;
    size_t base = (size_t)row * DMODEL;
    float x[3];
    #pragma unroll
    for (int l = 0; l < 3; l++) {
        int d = tid + l * 256;
        x[l] = h[base + d] + a[base + d];
    }
    float mean = block_reduce_sum(x[0] + x[1] + x[2]) * (1.f / DMODEL);
    float vs = 0.f;
    #pragma unroll
    for (int l = 0; l < 3; l++) { float dd = x[l] - mean; vs += dd * dd; }
    float rstd = rsqrtf(block_reduce_sum(vs) * (1.f / DMODEL) + 1e-12f);
    #pragma unroll
    for (int l = 0; l < 3; l++) {
        int d = tid + l * 256;
        float y = (x[l] - mean) * rstd * g[d] + b[d];
        h[base + d] = y;
        __nv_bfloat16 hi, lo; split_bf16(y, hi, lo);
        hhi[base + d] = hi; hlo[base + d] = lo;
    }
}

// ---------------------------------------------------------------------------
// Split-bf16 HMMA GEMM: 2-stage cp.async double buffer, 2 CTAs/SM,
// single __syncthreads per k-tile (load issued after the sync).
// ---------------------------------------------------------------------------
#define TILE_B (128 * 40 * 2)          // 10240 bytes per tile
#define SMEMSZ (8 * TILE_B)            // 2 stages x 4 tiles = 81920

__global__ void __launch_bounds__(256, 2) mma_gemm(
    const __nv_bfloat16* __restrict__ Ahi, const __nv_bfloat16* __restrict__ Alo,
    const __nv_bfloat16* __restrict__ Bhi, const __nv_bfloat16* __restrict__ Blo,
    const float* __restrict__ bias, const float* __restrict__ bias2,
    const float* __restrict__ bias3,
    float* __restrict__ Cf, __nv_bfloat16* __restrict__ Chi, __nv_bfloat16* __restrict__ Clo,
    int M, int N, int K, int epi)
{
    extern __shared__ char smem[];
    uint32_t sbase = smem_u32(smem);
    int tid = threadIdx.x, lane = tid & 31, wid = tid >> 5;
    int wm = wid & 3, wn = wid >> 2;
    int bm = blockIdx.y * 128, bn = blockIdx.x * 128;
    int nkt = K >> 5;

    float acc[2][8][4] = {};

    int lrow = tid >> 2;
    int lc16 = tid & 3;

    auto load_stage = [&](int buf, int kt) {
        int kb = kt * 32 + lc16 * 8;
        uint32_t dbase = sbase + buf * (4 * TILE_B);
        #pragma unroll
        for (int c = 0; c < 2; c++) {
            int row = lrow + c * 64;
            uint32_t so = (uint32_t)(row * 80 + lc16 * 16);
            CP_ASYNC16(dbase + 0 * TILE_B + so, Ahi + (size_t)(bm + row) * K + kb);
            CP_ASYNC16(dbase + 1 * TILE_B + so, Alo + (size_t)(bm + row) * K + kb);
            CP_ASYNC16(dbase + 2 * TILE_B + so, Bhi + (size_t)(bn + row) * K + kb);
            CP_ASYNC16(dbase + 3 * TILE_B + so, Blo + (size_t)(bn + row) * K + kb);
        }
        CP_COMMIT();
    };

    load_stage(0, 0);

    for (int kt = 0; kt < nkt; kt++) {
        CP_WAIT(0);
        __syncthreads();                 // stage kt visible; all warps done with buf (kt+1)&1
        if (kt + 1 < nkt) load_stage((kt + 1) & 1, kt + 1);

        uint32_t abase = sbase + (uint32_t)(kt & 1) * (4 * TILE_B);
        #pragma unroll
        for (int ks = 0; ks < 2; ks++) {
            uint32_t koff = (uint32_t)((ks * 16 + (lane >> 4) * 8) * 2);
            uint32_t ah[2][4], al[2][4];
            #pragma unroll
            for (int mt = 0; mt < 2; mt++) {
                uint32_t r = abase + (uint32_t)((wm * 32 + mt * 16 + (lane & 15)) * 80) + koff;
                ldsm_x4(ah[mt], r);
                ldsm_x4(al[mt], r + TILE_B);
            }
            uint32_t bh[2][4], bl[2][4];
            {
                uint32_t r = abase + 2 * TILE_B
                           + (uint32_t)((wn * 64 + (lane & 15)) * 80) + koff;
                ldsm_x4(bh[0], r);
                ldsm_x4(bl[0], r + TILE_B);
            }
            #pragma unroll
            for (int nt = 0; nt < 4; nt++) {
                int c = nt & 1;
                if (nt < 3) {
                    uint32_t r = abase + 2 * TILE_B
                               + (uint32_t)((wn * 64 + (nt + 1) * 16 + (lane & 15)) * 80) + koff;
                    ldsm_x4(bh[c ^ 1], r);
                    ldsm_x4(bl[c ^ 1], r + TILE_B);
                }
                #pragma unroll
                for (int mt = 0; mt < 2; mt++) {
                    mma_bf16(acc[mt][nt * 2 + 0], ah[mt], bh[c][0], bh[c][2]);
                    mma_bf16(acc[mt][nt * 2 + 0], ah[mt], bl[c][0], bl[c][2]);
                    mma_bf16(acc[mt][nt * 2 + 0], al[mt], bh[c][0], bh[c][2]);
                    mma_bf16(acc[mt][nt * 2 + 1], ah[mt], bh[c][1], bh[c][3]);
                    mma_bf16(acc[mt][nt * 2 + 1], ah[mt], bl[c][1], bl[c][3]);
                    mma_bf16(acc[mt][nt * 2 + 1], al[mt], bh[c][1], bh[c][3]);
                }
            }
        }
    }

    int g = lane >> 2, t4 = lane & 3;
    #pragma unroll
    for (int mt = 0; mt < 2; mt++) {
        #pragma unroll
        for (int nt = 0; nt < 4; nt++) {
            #pragma unroll
            for (int h8 = 0; h8 < 2; h8++) {
                float* d = acc[mt][nt * 2 + h8];
                int c0 = bn + wn * 64 + nt * 16 + h8 * 8 + t4 * 2;
                #pragma unroll
                for (int rr = 0; rr < 2; rr++) {
                    int r = bm + wm * 32 + mt * 16 + g + rr * 8;
                    float v0 = d[rr * 2 + 0], v1 = d[rr * 2 + 1];
                    if (epi == 3) {
                        if (c0 < DMODEL) {
                            v0 = (v0 + __ldg(bias + c0)) * 0.125f;
                            v1 = (v1 + __ldg(bias + c0 + 1)) * 0.125f;
                        } else if (c0 < 2 * DMODEL) {
                            v0 += __ldg(bias2 + c0 - DMODEL);
                            v1 += __ldg(bias2 + c0 + 1 - DMODEL);
                        } else {
                            v0 += __ldg(bias3 + c0 - 2 * DMODEL);
                            v1 += __ldg(bias3 + c0 + 1 - 2 * DMODEL);
                        }
                    } else if (bias) {
                        v0 += __ldg(bias + c0);
                        v1 += __ldg(bias + c0 + 1);
                    }
                    if (epi == 2) {
                        v0 = 0.5f * v0 * (1.f + erff(v0 * 0.7071067811865476f));
                        v1 = 0.5f * v1 * (1.f + erff(v1 * 0.7071067811865476f));
                        __nv_bfloat16 h0, l0, h1, l1;
                        split_bf16(v0, h0, l0); split_bf16(v1, h1, l1);
                        size_t idx = (size_t)r * N + c0;
                        *(__nv_bfloat162*)&Chi[idx] = __nv_bfloat162(h0, h1);
                        *(__nv_bfloat162*)&Clo[idx] = __nv_bfloat162(l0, l1);
                        continue;
                    }
                    float2 o; o.x = v0; o.y = v1;
                    *(float2*)&Cf[(size_t)r * N + c0] = o;
                }
            }
        }
    }
}

// ---------------------------------------------------------------------------
// Sliding-window attention v6 (kept from round 12): mma flash attention,
// V staged row-major, consumed via ldmatrix.trans.
// ---------------------------------------------------------------------------
#define AKOFF_LO 4608
#define AVOFF    9216
#define AQOFF_LO 9216

__global__ void __launch_bounds__(128, 3) local_attn_kernel(
    const float* __restrict__ QKV, const int* __restrict__ mask,
    __nv_bfloat16* __restrict__ Ohi, __nv_bfloat16* __restrict__ Olo,
    int nc, int S, int row_base)
{
    __shared__ char  sbuf[18432];
    __shared__ float sbias[3 * CHUNK];
    __shared__ int   skpos[3 * CHUNK];

    int nb = blockIdx.x;
    int n = nb >> 2, qt = nb & 3;
    int h = blockIdx.y, b = blockIdx.z;
    int tid = threadIdx.x;
    int lane = tid & 31, w = tid >> 5;
    int g = lane >> 2, t4 = lane & 3;
    uint32_t sb32 = smem_u32(sbuf);

    #pragma unroll
    for (int jj = 0; jj < 6; jj++) {
        int j = tid + jj * 128;
        int cn = n - 1 + (j >> 8);
        bool cv = (cn >= 0) && (cn < nc);
        int cnc = min(max(cn, 0), nc - 1);
        int kpos = cnc * CHUNK + (j & 255);
        sbias[j] = (cv && mask[b * S + kpos] != 0) ? 0.f : -1e30f;
        skpos[j] = kpos;
    }

    // stage Q: 64 rows x 64 dims, hi/lo, 144B pitch
    {
        int row = tid >> 1, half = tid & 1;
        const float* src = QKV + (size_t)(row_base + b * S + n * CHUNK + qt * 64 + row) * NQKV
                         + h * DHEAD + half * 32;
        float f[32];
        #pragma unroll
        for (int e = 0; e < 8; e++) {
            float4 t = *(const float4*)(src + e * 4);
            f[e*4+0] = t.x; f[e*4+1] = t.y; f[e*4+2] = t.z; f[e*4+3] = t.w;
        }
        uint32_t hi[16], lo[16];
        #pragma unroll
        for (int e = 0; e < 16; e++) split_pack2(f[2*e], f[2*e+1], hi[e], lo[e]);
        char* dst = sbuf + row * 144 + half * 64;
        #pragma unroll
        for (int e = 0; e < 4; e++) {
            *(uint4*)(dst + e * 16) = make_uint4(hi[e*4], hi[e*4+1], hi[e*4+2], hi[e*4+3]);
            *(uint4*)(dst + AQOFF_LO + e * 16) = make_uint4(lo[e*4], lo[e*4+1], lo[e*4+2], lo[e*4+3]);
        }
    }
    __syncthreads();

    uint32_t qh[4][4], ql[4][4];
    #pragma unroll
    for (int kc = 0; kc < 4; kc++) {
        uint32_t addr = sb32 + (uint32_t)((w * 16 + (lane & 15)) * 144 + kc * 32 + (lane >> 4) * 16);
        ldsm_x4(qh[kc], addr);
        ldsm_x4(ql[kc], addr + AQOFF_LO);
    }

    float m0 = -1e30f, m1 = -1e30f, l0 = 0.f, l1 = 0.f;
    float O[8][4] = {};

    int jlo = (n == 0) ? CHUNK : 0;
    int jhi = (n == nc - 1) ? (2 * CHUNK - 1) : (3 * CHUNK - 1);
    int wq0 = qt * 64 + w * 16;
    int wjs = max(wq0, jlo), wje = min(wq0 + 15 + WINW, jhi);
    int bjs = max(qt * 64, jlo), bje = min(qt * 64 + 63 + WINW, jhi);
    int iq0 = wq0 + g, iq1 = iq0 + 8;

    const float* kvb = QKV + (size_t)(row_base + b * S) * NQKV + DMODEL + h * DHEAD;

    for (int t0 = bjs & ~31; t0 <= bje; t0 += 32) {
        __syncthreads();
        // stage K and V, both [32 keys x 64 dims] hi/lo, 144B pitch
        {
            int key = tid >> 2, dg = tid & 3;
            int j = min(t0 + key, 3 * CHUNK - 1);
            const float* src = kvb + (size_t)skpos[j] * NQKV + dg * 16;
            float f[16];
            #pragma unroll
            for (int e = 0; e < 4; e++) {
                float4 t = *(const float4*)(src + e * 4);
                f[e*4+0] = t.x; f[e*4+1] = t.y; f[e*4+2] = t.z; f[e*4+3] = t.w;
            }
            uint32_t hi[8], lo[8];
            #pragma unroll
            for (int e = 0; e < 8; e++) split_pack2(f[2*e], f[2*e+1], hi[e], lo[e]);
            char* kdst = sbuf + key * 144 + dg * 32;
            *(uint4*)(kdst)                 = make_uint4(hi[0], hi[1], hi[2], hi[3]);
            *(uint4*)(kdst + 16)            = make_uint4(hi[4], hi[5], hi[6], hi[7]);
            *(uint4*)(kdst + AKOFF_LO)      = make_uint4(lo[0], lo[1], lo[2], lo[3]);
            *(uint4*)(kdst + AKOFF_LO + 16) = make_uint4(lo[4], lo[5], lo[6], lo[7]);
            const float* vsrc = src + DMODEL;
            #pragma unroll
            for (int e = 0; e < 4; e++) {
                float4 t = *(const float4*)(vsrc + e * 4);
                f[e*4+0] = t.x; f[e*4+1] = t.y; f[e*4+2] = t.z; f[e*4+3] = t.w;
            }
            #pragma unroll
            for (int e = 0; e < 8; e++) split_pack2(f[2*e], f[2*e+1], hi[e], lo[e]);
            char* vdst = sbuf + AVOFF + key * 144 + dg * 32;
            *(uint4*)(vdst)               = make_uint4(hi[0], hi[1], hi[2], hi[3]);
            *(uint4*)(vdst + 16)          = make_uint4(hi[4], hi[5], hi[6], hi[7]);
            *(uint4*)(vdst + 4608)        = make_uint4(lo[0], lo[1], lo[2], lo[3]);
            *(uint4*)(vdst + 4608 + 16)   = make_uint4(lo[4], lo[5], lo[6], lo[7]);
        }
        __syncthreads();

        if (t0 + 31 < wjs || t0 > wje) continue;

        // --- scores S[16 x 32] ---
        float Sc[4][4];
        #pragma unroll
        for (int tt = 0; tt < 4; tt++)
            #pragma unroll
            for (int e = 0; e < 4; e++) Sc[tt][e] = 0.f;

        #pragma unroll
        for (int kc = 0; kc < 4; kc++) {
            #pragma unroll
            for (int kh = 0; kh < 2; kh++) {
                uint32_t bh[4], bl[4];
                uint32_t addr = sb32 + (uint32_t)((kh * 16 + (lane & 15)) * 144 + kc * 32 + (lane >> 4) * 16);
                ldsm_x4(bh, addr);
                ldsm_x4(bl, addr + AKOFF_LO);
                int t = kh * 2;
                mma_bf16(Sc[t],     qh[kc], bh[0], bh[2]);
                mma_bf16(Sc[t],     qh[kc], bl[0], bl[2]);
                mma_bf16(Sc[t],     ql[kc], bh[0], bh[2]);
                mma_bf16(Sc[t + 1], qh[kc], bh[1], bh[3]);
                mma_bf16(Sc[t + 1], qh[kc], bl[1], bl[3]);
                mma_bf16(Sc[t + 1], ql[kc], bh[1], bh[3]);
            }
        }

        // --- mask + row max ---
        float rm0 = -1e30f, rm1 = -1e30f;
        #pragma unroll
        for (int tt = 0; tt < 4; tt++) {
            int j0 = t0 + tt * 8 + 2 * t4, j1 = j0 + 1;
            float sb0 = sbias[min(j0, 3 * CHUNK - 1)];
            float sb1 = sbias[min(j1, 3 * CHUNK - 1)];
            bool v00 = (sb0 == 0.f) && (j0 >= iq0) && (j0 <= iq0 + WINW);
            bool v01 = (sb1 == 0.f) && (j1 >= iq0) && (j1 <= iq0 + WINW);
            bool v10 = (sb0 == 0.f) && (j0 >= iq1) && (j0 <= iq1 + WINW);
            bool v11 = (sb1 == 0.f) && (j1 >= iq1) && (j1 <= iq1 + WINW);
            Sc[tt][0] = v00 ? Sc[tt][0] : -1e30f;
            Sc[tt][1] = v01 ? Sc[tt][1] : -1e30f;
            Sc[tt][2] = v10 ? Sc[tt][2] : -1e30f;
            Sc[tt][3] = v11 ? Sc[tt][3] : -1e30f;
            rm0 = fmaxf(rm0, fmaxf(Sc[tt][0], Sc[tt][1]));
            rm1 = fmaxf(rm1, fmaxf(Sc[tt][2], Sc[tt][3]));
        }
        rm0 = fmaxf(rm0, __shfl_xor_sync(0xffffffffu, rm0, 1));
        rm0 = fmaxf(rm0, __shfl_xor_sync(0xffffffffu, rm0, 2));
        rm1 = fmaxf(rm1, __shfl_xor_sync(0xffffffffu, rm1, 1));
        rm1 = fmaxf(rm1, __shfl_xor_sync(0xffffffffu, rm1, 2));

        float mn0 = fmaxf(m0, rm0), mn1 = fmaxf(m1, rm1);
        float c0 = __expf(m0 - mn0), c1 = __expf(m1 - mn1);
        l0 *= c0; l1 *= c1;
        #pragma unroll
        for (int dt = 0; dt < 8; dt++) {
            O[dt][0] *= c0; O[dt][1] *= c0;
            O[dt][2] *= c1; O[dt][3] *= c1;
        }
        m0 = mn0; m1 = mn1;

        float rs0 = 0.f, rs1 = 0.f;
        #pragma unroll
        for (int tt = 0; tt < 4; tt++) {
            float p0 = (Sc[tt][0] > -5e29f) ? __expf(Sc[tt][0] - m0) : 0.f;
            float p1 = (Sc[tt][1] > -5e29f) ? __expf(Sc[tt][1] - m0) : 0.f;
            float p2 = (Sc[tt][2] > -5e29f) ? __expf(Sc[tt][2] - m1) : 0.f;
            float p3 = (Sc[tt][3] > -5e29f) ? __expf(Sc[tt][3] - m1) : 0.f;
            Sc[tt][0] = p0; Sc[tt][1] = p1; Sc[tt][2] = p2; Sc[tt][3] = p3;
            rs0 += p0 + p1; rs1 += p2 + p3;
        }
        rs0 += __shfl_xor_sync(0xffffffffu, rs0, 1);
        rs0 += __shfl_xor_sync(0xffffffffu, rs0, 2);
        rs1 += __shfl_xor_sync(0xffffffffu, rs1, 1);
        rs1 += __shfl_xor_sync(0xffffffffu, rs1, 2);
        l0 += rs0; l1 += rs1;

        // --- P @ V via trans-ldsm B fragments ---
        #pragma unroll
        for (int kc2 = 0; kc2 < 2; kc2++) {
            int ta = kc2 * 2, tb = ta + 1;
            uint32_t ah[4], al[4];
            split_pack2(Sc[ta][0], Sc[ta][1], ah[0], al[0]);
            split_pack2(Sc[ta][2], Sc[ta][3], ah[1], al[1]);
            split_pack2(Sc[tb][0], Sc[tb][1], ah[2], al[2]);
            split_pack2(Sc[tb][2], Sc[tb][3], ah[3], al[3]);
            uint32_t vrow = (uint32_t)(kc2 * 16 + (lane & 7) + ((lane & 16) ? 8 : 0));
            #pragma unroll
            for (int dt = 0; dt < 4; dt++) {
                uint32_t bh[4], bl[4];
                uint32_t addr = sb32 + AVOFF + vrow * 144
                              + (uint32_t)(dt * 32 + ((lane & 8) ? 16 : 0));
                ldsm_x4_trans(bh, addr);
                ldsm_x4_trans(bl, addr + 4608);
                mma_bf16(O[dt * 2],     ah, bh[0], bh[2]);
                mma_bf16(O[dt * 2],     ah, bl[0], bl[2]);
                mma_bf16(O[dt * 2],     al, bh[0], bh[2]);
                mma_bf16(O[dt * 2 + 1], ah, bh[1], bh[3]);
                mma_bf16(O[dt * 2 + 1], ah, bl[1], bl[3]);
                mma_bf16(O[dt * 2 + 1], al, bh[1], bh[3]);
            }
        }
    }

    float inv0 = 1.f / l0, inv1 = 1.f / l1;
    int qrow0 = row_base + b * S + n * CHUNK + wq0 + g;
    #pragma unroll
    for (int dt = 0; dt < 8; dt++) {
        int col = h * DHEAD + dt * 8 + 2 * t4;
        size_t i0 = (size_t)qrow0 * DMODEL + col;
        size_t i1 = i0 + (size_t)8 * DMODEL;
        float a0 = O[dt][0] * inv0, a1 = O[dt][1] * inv0;
        float b0 = O[dt][2] * inv1, b1 = O[dt][3] * inv1;
        __nv_bfloat16 h0, lo0, h1, lo1;
        split_bf16(a0, h0, lo0); split_bf16(a1, h1, lo1);
        *(__nv_bfloat162*)&Ohi[i0] = __nv_bfloat162(h0, h1);
        *(__nv_bfloat162*)&Olo[i0] = __nv_bfloat162(lo0, lo1);
        split_bf16(b0, h0, lo0); split_bf16(b1, h1, lo1);
        *(__nv_bfloat162*)&Ohi[i1] = __nv_bfloat162(h0, h1);
        *(__nv_bfloat162*)&Olo[i1] = __nv_bfloat162(lo0, lo1);
    }
}

// ---------------------------------------------------------------------------
// Interaction head
// ---------------------------------------------------------------------------
__global__ void init_re_kernel(float* __restrict__ re)
{
    re[blockIdx.x * 256 + threadIdx.x] = 0.f;
}

__global__ void __launch_bounds__(256) softmax_max_kernel(
    const float* __restrict__ P, float* __restrict__ re)
{
    int row = blockIdx.x, tid = threadIdx.x;
    int b = row / CLEN;
    const float* p = P + (size_t)row * QLEN;
    float x0 = p[tid], x1 = p[tid + 256];
    float m = block_reduce_max(fmaxf(x0, x1));
    float e0 = __expf(x0 - m), e1 = __expf(x1 - m);
    float s = block_reduce_sum(e0 + e1);
    float inv = 1.f / s;
    unsigned* r = (unsigned*)(re + b * QLEN);
    atomicMax(r + tid,       __float_as_uint(e0 * inv));
    atomicMax(r + tid + 256, __float_as_uint(e1 * inv));
}

__global__ void fc_kernel(const float* __restrict__ re, const float* __restrict__ w,
                          const float* __restrict__ bfc, float* __restrict__ out)
{
    int t = threadIdx.x;
    if (t >= 8) return;
    int b = t >> 2, o = t & 3;
    float s = bfc[o];
    for (int q = 0; q < QLEN; q++) s += re[b * QLEN + q] * w[q * 4 + o];
    out[b * 4 + o] = s;
}

// ---------------------------------------------------------------------------
// Host orchestration
// ---------------------------------------------------------------------------
extern "C" void kernel_launch(void* const* d_in, const int* in_sizes, int n_in,
                              void* d_out, int out_size)
{
    const int*   q_ids    = (const int*)  d_in[0];
    const int*   c_ids    = (const int*)  d_in[1];
    const int*   q_mask   = (const int*)  d_in[2];
    const int*   c_mask   = (const int*)  d_in[3];
    const float* word_emb = (const float*)d_in[4];
    const float* pos_emb  = (const float*)d_in[5];
    const float* type_emb = (const float*)d_in[6];
    const float* eg       = (const float*)d_in[7];
    const float* eb       = (const float*)d_in[8];
    const float* Wq  = (const float*)d_in[9];
    const float* bq  = (const float*)d_in[10];
    const float* Wk  = (const float*)d_in[11];
    const float* bk  = (const float*)d_in[12];
    const float* Wv  = (const float*)d_in[13];
    const float* bv  = (const float*)d_in[14];
    const float* Wo  = (const float*)d_in[15];
    const float* bo  = (const float*)d_in[16];
    const float* l1g = (const float*)d_in[17];
    const float* l1b = (const float*)d_in[18];
    const float* W1  = (const float*)d_in[19];
    const float* b1  = (const float*)d_in[20];
    const float* W2  = (const float*)d_in[21];
    const float* b2  = (const float*)d_in[22];
    const float* l2g = (const float*)d_in[23];
    const float* l2b = (const float*)d_in[24];
    const float* fcw = (const float*)d_in[25];
    const float* fcb = (const float*)d_in[26];

    cudaFuncSetAttribute(mma_gemm, cudaFuncAttributeMaxDynamicSharedMemorySize, SMEMSZ);

    __nv_bfloat16 *wqkvhi, *wqkvlo, *wohi, *wolo, *w1hi, *w1lo, *w2hi, *w2lo;
    __nv_bfloat16 *hhi, *hlo, *sthi, *stlo, *ffnhi, *ffnlo;
    float *h, *qkv, *t2, *ssc, *sre;
    cudaGetSymbolAddress((void**)&wqkvhi, g_wqkv_hi);
    cudaGetSymbolAddress((void**)&wqkvlo, g_wqkv_lo);
    cudaGetSymbolAddress((void**)&wohi,   g_wo_hi);
    cudaGetSymbolAddress((void**)&wolo,   g_wo_lo);
    cudaGetSymbolAddress((void**)&w1hi,   g_w1_hi);
    cudaGetSymbolAddress((void**)&w1lo,   g_w1_lo);
    cudaGetSymbolAddress((void**)&w2hi,   g_w2_hi);
    cudaGetSymbolAddress((void**)&w2lo,   g_w2_lo);
    cudaGetSymbolAddress((void**)&h,      g_h);
    cudaGetSymbolAddress((void**)&hhi,    g_h_hi);
    cudaGetSymbolAddress((void**)&hlo,    g_h_lo);
    cudaGetSymbolAddress((void**)&qkv,    g_qkv);
    cudaGetSymbolAddress((void**)&t2,     g_t2);
    cudaGetSymbolAddress((void**)&sthi,   g_st_hi);
    cudaGetSymbolAddress((void**)&stlo,   g_st_lo);
    cudaGetSymbolAddress((void**)&ffnhi,  g_ffn_hi);
    cudaGetSymbolAddress((void**)&ffnlo,  g_ffn_lo);
    cudaGetSymbolAddress((void**)&ssc,    g_sc);
    cudaGetSymbolAddress((void**)&sre,    g_re);

    dim3 gQKV(NQKV/128,   ROWSA/128);
    dim3 gD  (DMODEL/128, ROWSA/128);
    dim3 gF  (FFDIM/128,  ROWSA/128);
    dim3 gAc(4*CLEN/CHUNK, NHEAD, BATCH);
    dim3 gAq(4*QLEN/CHUNK, NHEAD, BATCH);

    // 0: QKV weight prep
    wprep_qkv_all<<<dim3(24, 24, 36), 256>>>(Wq, Wk, Wv, wqkvhi, wqkvlo);
    // 1: merged embedding
    embed_ln_all<<<ROWSA, 256>>>(c_ids, q_ids, word_emb, pos_emb, type_emb,
                                 eg, eb, h, hhi, hlo);
    // 2: Wo prep (keeps idx 3 = GEMM for the profiler)
    wprep_b<<<dim3(24, 24, NL), 256>>>(Wo, wohi, wolo, DMODEL, DMODEL);
    // 3: layer-0 merged QKV GEMM (profiling target)
    mma_gemm<<<gQKV, 256, SMEMSZ>>>(hhi, hlo, wqkvhi, wqkvlo,
        bq, bk, bv, qkv, nullptr, nullptr, ROWSA, NQKV, DMODEL, 3);
    // 4-5: layer-0 attention
    local_attn_kernel<<<gAc, 128>>>(qkv, c_mask, sthi, stlo, CLEN/CHUNK, CLEN, 0);
    local_attn_kernel<<<gAq, 128>>>(qkv, q_mask, sthi, stlo, QLEN/CHUNK, QLEN, QBASE);
    // 6-7: remaining weight prep
    wprep_b<<<dim3(96, 24, NL), 256>>>(W1, w1hi, w1lo, DMODEL, FFDIM);
    wprep_b<<<dim3(24, 96, NL), 256>>>(W2, w2hi, w2lo, FFDIM, DMODEL);

    for (int l = 0; l < NL; l++) {
        if (l > 0) {
            size_t qb = (size_t)l * QKVW;
            mma_gemm<<<gQKV, 256, SMEMSZ>>>(hhi, hlo, wqkvhi + qb, wqkvlo + qb,
                bq + l*DMODEL, bk + l*DMODEL, bv + l*DMODEL,
                qkv, nullptr, nullptr, ROWSA, NQKV, DMODEL, 3);
            local_attn_kernel<<<gAc, 128>>>(qkv, c_mask, sthi, stlo, CLEN/CHUNK, CLEN, 0);
            local_attn_kernel<<<gAq, 128>>>(qkv, q_mask, sthi, stlo, QLEN/CHUNK, QLEN, QBASE);
        }
        mma_gemm<<<gD, 256, SMEMSZ>>>(sthi, stlo, wohi + l*D2, wolo + l*D2,
            bo + l*DMODEL, nullptr, nullptr, t2, nullptr, nullptr,
            ROWSA, DMODEL, DMODEL, 0);
        add_ln_kernel<<<ROWSA, 256>>>(h, t2, l1g + l*DMODEL, l1b + l*DMODEL, hhi, hlo);
        mma_gemm<<<gF, 256, SMEMSZ>>>(hhi, hlo, w1hi + l*DF, w1lo + l*DF,
            b1 + l*FFDIM, nullptr, nullptr, nullptr, ffnhi, ffnlo,
            ROWSA, FFDIM, DMODEL, 2);
        mma_gemm<<<gD, 256, SMEMSZ>>>(ffnhi, ffnlo, w2hi + l*DF, w2lo + l*DF,
            b2 + l*DMODEL, nullptr, nullptr, t2, nullptr, nullptr,
            ROWSA, DMODEL, FFDIM, 0);
        add_ln_kernel<<<ROWSA, 256>>>(h, t2, l2g + l*DMODEL, l2b + l*DMODEL, hhi, hlo);
    }

    // interaction
    for (int b = 0; b < BATCH; b++) {
        mma_gemm<<<dim3(QLEN/128, CLEN/128), 256, SMEMSZ>>>(
            hhi + (size_t)b*CLEN*DMODEL, hlo + (size_t)b*CLEN*DMODEL,
            hhi + (size_t)(QBASE + b*QLEN)*DMODEL, hlo + (size_t)(QBASE + b*QLEN)*DMODEL,
            nullptr, nullptr, nullptr,
            ssc + (size_t)b*CLEN*QLEN, nullptr, nullptr,
            CLEN, QLEN, DMODEL, 0);
    }
    init_re_kernel<<<BATCH * QLEN / 256, 256>>>(sre);
    softmax_max_kernel<<<BATCH * CLEN, 256>>>(ssc, sre);
    fc_kernel<<<1, 32>>>(sre, fcw, fcb, (float*)d_out);
}

// round 14
// speedup vs baseline: 1.1611x; 1.0453x over previous
#include <cuda_runtime.h>
#include <cuda_bf16.h>
#include <math.h>
#include <stdint.h>

// ---------------------------------------------------------------------------
// Problem constants
// ---------------------------------------------------------------------------
#define NL     12
#define DMODEL 768
#define NHEAD  12
#define DHEAD  64
#define FFDIM  3072
#define BATCH  2
#define QLEN   512
#define CLEN   2048
#define CHUNK  256
#define WINW   512
#define NQKV   2304
#define CROWS  (BATCH * CLEN)
#define QROWS  (BATCH * QLEN)
#define ROWSA  (CROWS + QROWS)
#define QBASE  CROWS

// ---------------------------------------------------------------------------
// PTX helpers
// ---------------------------------------------------------------------------
__device__ __forceinline__ uint32_t smem_u32(const void* p) {
    uint32_t a;
    asm("{ .reg .u64 t; cvta.to.shared.u64 t, %1; cvt.u32.u64 %0, t; }" : "=r"(a) : "l"(p));
    return a;
}
__device__ __forceinline__ void ldsm_x4(uint32_t* r, uint32_t addr) {
    asm volatile("ldmatrix.sync.aligned.m8n8.x4.shared.b16 {%0,%1,%2,%3}, [%4];"
                 : "=r"(r[0]), "=r"(r[1]), "=r"(r[2]), "=r"(r[3]) : "r"(addr));
}
__device__ __forceinline__ void ldsm_x4_trans(uint32_t* r, uint32_t addr) {
    asm volatile("ldmatrix.sync.aligned.m8n8.x4.trans.shared.b16 {%0,%1,%2,%3}, [%4];"
                 : "=r"(r[0]), "=r"(r[1]), "=r"(r[2]), "=r"(r[3]) : "r"(addr));
}
__device__ __forceinline__ void mma_bf16(float* c, const uint32_t* a, uint32_t b0, uint32_t b1) {
    asm volatile(
        "mma.sync.aligned.m16n8k16.row.col.f32.bf16.bf16.f32 "
        "{%0,%1,%2,%3}, {%4,%5,%6,%7}, {%8,%9}, {%0,%1,%2,%3};"
        : "+f"(c[0]), "+f"(c[1]), "+f"(c[2]), "+f"(c[3])
        : "r"(a[0]), "r"(a[1]), "r"(a[2]), "r"(a[3]), "r"(b0), "r"(b1));
}
#define CP_ASYNC16(dst, src) \
    asm volatile("cp.async.cg.shared.global [%0], [%1], 16;" :: "r"(dst), "l"(src))
#define CP_COMMIT() asm volatile("cp.async.commit_group;")
#define CP_WAIT(n)  asm volatile("cp.async.wait_group %0;" :: "n"(n))

// ---------------------------------------------------------------------------
// Scratch (device globals)
// ---------------------------------------------------------------------------
#define D2   ((size_t)DMODEL * DMODEL)
#define DF   ((size_t)DMODEL * FFDIM)
#define QKVW (3ull * D2)

__device__ __nv_bfloat16 g_wqkv_hi[12 * QKVW];
__device__ __nv_bfloat16 g_wqkv_lo[12 * QKVW];
__device__ __nv_bfloat16 g_wo_hi[12 * D2];
__device__ __nv_bfloat16 g_wo_lo[12 * D2];
__device__ __nv_bfloat16 g_w1_hi[12 * DF];
__device__ __nv_bfloat16 g_w1_lo[12 * DF];
__device__ __nv_bfloat16 g_w2_hi[12 * DF];
__device__ __nv_bfloat16 g_w2_lo[12 * DF];

__device__ float g_h [ROWSA * DMODEL];
__device__ __nv_bfloat16 g_h_hi[ROWSA * DMODEL];
__device__ __nv_bfloat16 g_h_lo[ROWSA * DMODEL];
__device__ __nv_bfloat16 g_qkv_hi[(size_t)ROWSA * NQKV];
__device__ __nv_bfloat16 g_qkv_lo[(size_t)ROWSA * NQKV];
__device__ float g_t2 [ROWSA * DMODEL];
__device__ __nv_bfloat16 g_st_hi[ROWSA * DMODEL];
__device__ __nv_bfloat16 g_st_lo[ROWSA * DMODEL];
__device__ __nv_bfloat16 g_ffn_hi[ROWSA * FFDIM];
__device__ __nv_bfloat16 g_ffn_lo[ROWSA * FFDIM];

__device__ float g_sc [BATCH * CLEN * QLEN];
__device__ float g_re [BATCH * QLEN];

// ---------------------------------------------------------------------------
// Reductions
// ---------------------------------------------------------------------------
__device__ __forceinline__ float block_reduce_sum(float v) {
    __shared__ float sh[33];
    int lane = threadIdx.x & 31, wid = threadIdx.x >> 5;
    #pragma unroll
    for (int o = 16; o; o >>= 1) v += __shfl_xor_sync(0xffffffffu, v, o);
    if (lane == 0) sh[wid] = v;
    __syncthreads();
    if (wid == 0) {
        float t = (lane < 8) ? sh[lane] : 0.f;
        #pragma unroll
        for (int o = 4; o; o >>= 1) t += __shfl_xor_sync(0xffffffffu, t, o);
        if (lane == 0) sh[32] = t;
    }
    __syncthreads();
    float r = sh[32];
    __syncthreads();
    return r;
}
__device__ __forceinline__ float block_reduce_max(float v) {
    __shared__ float sh[33];
    int lane = threadIdx.x & 31, wid = threadIdx.x >> 5;
    #pragma unroll
    for (int o = 16; o; o >>= 1) v = fmaxf(v, __shfl_xor_sync(0xffffffffu, v, o));
    if (lane == 0) sh[wid] = v;
    __syncthreads();
    if (wid == 0) {
        float t = (lane < 8) ? sh[lane] : -1e30f;
        #pragma unroll
        for (int o = 4; o; o >>= 1) t = fmaxf(t, __shfl_xor_sync(0xffffffffu, t, o));
        if (lane == 0) sh[32] = t;
    }
    __syncthreads();
    float r = sh[32];
    __syncthreads();
    return r;
}

__device__ __forceinline__ void split_bf16(float x, __nv_bfloat16& hi, __nv_bfloat16& lo) {
    hi = __float2bfloat16(x);
    lo = __float2bfloat16(x - __bfloat162float(hi));
}
__device__ __forceinline__ void split_pack2(float a, float b, uint32_t& hi, uint32_t& lo) {
    __nv_bfloat16 ah, al, bh, bl;
    split_bf16(a, ah, al); split_bf16(b, bh, bl);
    __nv_bfloat162 H(ah, bh), L(al, bl);
    hi = *(uint32_t*)&H; lo = *(uint32_t*)&L;
}

// ---------------------------------------------------------------------------
// Batched weight transpose + split
// ---------------------------------------------------------------------------
__global__ void __launch_bounds__(256) wprep_qkv_all(
    const float* __restrict__ Wq, const float* __restrict__ Wk,
    const float* __restrict__ Wv,
    __nv_bfloat16* __restrict__ Thi, __nv_bfloat16* __restrict__ Tlo)
{
    __shared__ float t[32][33];
    int z = blockIdx.z;
    int l = z / 3, which = z % 3;
    const float* W = (which == 0 ? Wq : (which == 1 ? Wk : Wv)) + (size_t)l * D2;
    __nv_bfloat16* ohi = Thi + (size_t)l * QKVW + (size_t)which * D2;
    __nv_bfloat16* olo = Tlo + (size_t)l * QKVW + (size_t)which * D2;
    int tx = threadIdx.x & 31, ty = threadIdx.x >> 5;
    int n0 = blockIdx.x * 32, k0 = blockIdx.y * 32;
    #pragma unroll
    for (int j = 0; j < 4; j++)
        t[ty + 8 * j][tx] = W[(size_t)(k0 + ty + 8 * j) * DMODEL + n0 + tx];
    __syncthreads();
    #pragma unroll
    for (int j = 0; j < 4; j++) {
        int n = n0 + ty + 8 * j, k = k0 + tx;
        __nv_bfloat16 hi, lo;
        split_bf16(t[tx][ty + 8 * j], hi, lo);
        ohi[(size_t)n * DMODEL + k] = hi;
        olo[(size_t)n * DMODEL + k] = lo;
    }
}

__global__ void __launch_bounds__(256) wprep_b(
    const float* __restrict__ W, __nv_bfloat16* __restrict__ Thi,
    __nv_bfloat16* __restrict__ Tlo, int K, int N)
{
    __shared__ float t[32][33];
    size_t l = blockIdx.z;
    const float* Wl = W + l * (size_t)K * N;
    __nv_bfloat16* ohi = Thi + l * (size_t)K * N;
    __nv_bfloat16* olo = Tlo + l * (size_t)K * N;
    int tx = threadIdx.x & 31, ty = threadIdx.x >> 5;
    int n0 = blockIdx.x * 32, k0 = blockIdx.y * 32;
    #pragma unroll
    for (int j = 0; j < 4; j++)
        t[ty + 8 * j][tx] = Wl[(size_t)(k0 + ty + 8 * j) * N + n0 + tx];
    __syncthreads();
    #pragma unroll
    for (int j = 0; j < 4; j++) {
        int n = n0 + ty + 8 * j, k = k0 + tx;
        __nv_bfloat16 hi, lo;
        split_bf16(t[tx][ty + 8 * j], hi, lo);
        ohi[(size_t)n * K + k] = hi;
        olo[(size_t)n * K + k] = lo;
    }
}

// ---------------------------------------------------------------------------
// Merged embedding + LN
// ---------------------------------------------------------------------------
__global__ void __launch_bounds__(256) embed_ln_all(
    const int* __restrict__ c_ids, const int* __restrict__ q_ids,
    const float* __restrict__ we, const float* __restrict__ pe,
    const float* __restrict__ te,
    const float* __restrict__ g, const float* __restrict__ b,
    float* __restrict__ h, __nv_bfloat16* __restrict__ hhi,
    __nv_bfloat16* __restrict__ hlo)
{
    int row = blockIdx.x;
    const int* ids; int rlocal, S;
    if (row < CROWS) { ids = c_ids; rlocal = row;         S = CLEN; }
    else             { ids = q_ids; rlocal = row - CROWS; S = QLEN; }
    int s = rlocal % S;
    int tid = threadIdx.x;
    long long id = ids[rlocal];
    const float* w = we + id * DMODEL;
    float x[3];
    #pragma unroll
    for (int l = 0; l < 3; l++) {
        int d = tid + l * 256;
        x[l] = w[d] + pe[(size_t)s * DMODEL + d] + te[d];
    }
    float mean = block_reduce_sum(x[0] + x[1] + x[2]) * (1.f / DMODEL);
    float vs = 0.f;
    #pragma unroll
    for (int l = 0; l < 3; l++) { float dd = x[l] - mean; vs += dd * dd; }
    float rstd = rsqrtf(block_reduce_sum(vs) * (1.f / DMODEL) + 1e-12f);
    size_t base = (size_t)row * DMODEL;
    #pragma unroll
    for (int l = 0; l < 3; l++) {
        int d = tid + l * 256;
        float y = (x[l] - mean) * rstd * g[d] + b[d];
        h[base + d] = y;
        __nv_bfloat16 hi, lo; split_bf16(y, hi, lo);
        hhi[base + d] = hi; hlo[base + d] = lo;
    }
}

// h = LN(a); a already contains residual + projection (fused in GEMM epilogue)
__global__ void __launch_bounds__(256) add_ln_kernel(
    float* __restrict__ h, const float* __restrict__ a,
    const float* __restrict__ g, const float* __restrict__ b,
    __nv_bfloat16* __restrict__ hhi, __nv_bfloat16* __restrict__ hlo)
{
    int row = blockIdx.x;
    int tid = threadIdx.x;
    size_t base = (size_t)row * DMODEL;
    float x[3];
    #pragma unroll
    for (int l = 0; l < 3; l++) {
        int d = tid + l * 256;
        x[l] = a[base + d];
    }
    float mean = block_reduce_sum(x[0] + x[1] + x[2]) * (1.f / DMODEL);
    float vs = 0.f;
    #pragma unroll
    for (int l = 0; l < 3; l++) { float dd = x[l] - mean; vs += dd * dd; }
    float rstd = rsqrtf(block_reduce_sum(vs) * (1.f / DMODEL) + 1e-12f);
    #pragma unroll
    for (int l = 0; l < 3; l++) {
        int d = tid + l * 256;
        float y = (x[l] - mean) * rstd * g[d] + b[d];
        h[base + d] = y;
        __nv_bfloat16 hi, lo; split_bf16(y, hi, lo);
        hhi[base + d] = hi; hlo[base + d] = lo;
    }
}

// ---------------------------------------------------------------------------
// Split-bf16 HMMA GEMM: 2-stage cp.async, 2 CTAs/SM, single sync per k-tile,
// pointer-increment loads.
// epi: 0 = bias + fp32; 2 = bias + GELU + bf16 hi/lo;
//      3 = QKV tri-bias (+0.125 on q cols) + bf16 hi/lo; 4 = bias + residual + fp32
// ---------------------------------------------------------------------------
#define TILE_B (128 * 40 * 2)
#define SMEMSZ (8 * TILE_B)

__global__ void __launch_bounds__(256, 2) mma_gemm(
    const __nv_bfloat16* __restrict__ Ahi, const __nv_bfloat16* __restrict__ Alo,
    const __nv_bfloat16* __restrict__ Bhi, const __nv_bfloat16* __restrict__ Blo,
    const float* __restrict__ bias, const float* __restrict__ bias2,
    const float* __restrict__ bias3, const float* __restrict__ resid,
    float* __restrict__ Cf, __nv_bfloat16* __restrict__ Chi, __nv_bfloat16* __restrict__ Clo,
    int M, int N, int K, int epi)
{
    extern __shared__ char smem[];
    uint32_t sbase = smem_u32(smem);
    int tid = threadIdx.x, lane = tid & 31, wid = tid >> 5;
    int wm = wid & 3, wn = wid >> 2;
    int bm = blockIdx.y * 128, bn = blockIdx.x * 128;
    int nkt = K >> 5;

    float acc[2][8][4] = {};

    int lrow = tid >> 2;
    int lc16 = tid & 3;
    uint32_t so_c0 = (uint32_t)(lrow * 80 + lc16 * 16);
    uint32_t so_c1 = so_c0 + 64 * 80;

    const __nv_bfloat16* pa0h = Ahi + (size_t)(bm + lrow) * K + lc16 * 8;
    const __nv_bfloat16* pa1h = pa0h + (size_t)64 * K;
    const __nv_bfloat16* pa0l = Alo + (size_t)(bm + lrow) * K + lc16 * 8;
    const __nv_bfloat16* pa1l = pa0l + (size_t)64 * K;
    const __nv_bfloat16* pb0h = Bhi + (size_t)(bn + lrow) * K + lc16 * 8;
    const __nv_bfloat16* pb1h = pb0h + (size_t)64 * K;
    const __nv_bfloat16* pb0l = Blo + (size_t)(bn + lrow) * K + lc16 * 8;
    const __nv_bfloat16* pb1l = pb0l + (size_t)64 * K;

    auto load_stage = [&](int buf) {
        uint32_t dbase = sbase + buf * (4 * TILE_B);
        CP_ASYNC16(dbase + 0 * TILE_B + so_c0, pa0h);
        CP_ASYNC16(dbase + 0 * TILE_B + so_c1, pa1h);
        CP_ASYNC16(dbase + 1 * TILE_B + so_c0, pa0l);
        CP_ASYNC16(dbase + 1 * TILE_B + so_c1, pa1l);
        CP_ASYNC16(dbase + 2 * TILE_B + so_c0, pb0h);
        CP_ASYNC16(dbase + 2 * TILE_B + so_c1, pb1h);
        CP_ASYNC16(dbase + 3 * TILE_B + so_c0, pb0l);
        CP_ASYNC16(dbase + 3 * TILE_B + so_c1, pb1l);
        CP_COMMIT();
        pa0h += 32; pa1h += 32; pa0l += 32; pa1l += 32;
        pb0h += 32; pb1h += 32; pb0l += 32; pb1l += 32;
    };

    load_stage(0);

    for (int kt = 0; kt < nkt; kt++) {
        CP_WAIT(0);
        __syncthreads();
        if (kt + 1 < nkt) load_stage((kt + 1) & 1);

        uint32_t abase = sbase + (uint32_t)(kt & 1) * (4 * TILE_B);
        #pragma unroll
        for (int ks = 0; ks < 2; ks++) {
            uint32_t koff = (uint32_t)((ks * 16 + (lane >> 4) * 8) * 2);
            uint32_t ah[2][4], al[2][4];
            #pragma unroll
            for (int mt = 0; mt < 2; mt++) {
                uint32_t r = abase + (uint32_t)((wm * 32 + mt * 16 + (lane & 15)) * 80) + koff;
                ldsm_x4(ah[mt], r);
                ldsm_x4(al[mt], r + TILE_B);
            }
            uint32_t bh[2][4], bl[2][4];
            {
                uint32_t r = abase + 2 * TILE_B
                           + (uint32_t)((wn * 64 + (lane & 15)) * 80) + koff;
                ldsm_x4(bh[0], r);
                ldsm_x4(bl[0], r + TILE_B);
            }
            #pragma unroll
            for (int nt = 0; nt < 4; nt++) {
                int c = nt & 1;
                if (nt < 3) {
                    uint32_t r = abase + 2 * TILE_B
                               + (uint32_t)((wn * 64 + (nt + 1) * 16 + (lane & 15)) * 80) + koff;
                    ldsm_x4(bh[c ^ 1], r);
                    ldsm_x4(bl[c ^ 1], r + TILE_B);
                }
                #pragma unroll
                for (int mt = 0; mt < 2; mt++) {
                    mma_bf16(acc[mt][nt * 2 + 0], ah[mt], bh[c][0], bh[c][2]);
                    mma_bf16(acc[mt][nt * 2 + 0], ah[mt], bl[c][0], bl[c][2]);
                    mma_bf16(acc[mt][nt * 2 + 0], al[mt], bh[c][0], bh[c][2]);
                    mma_bf16(acc[mt][nt * 2 + 1], ah[mt], bh[c][1], bh[c][3]);
                    mma_bf16(acc[mt][nt * 2 + 1], ah[mt], bl[c][1], bl[c][3]);
                    mma_bf16(acc[mt][nt * 2 + 1], al[mt], bh[c][1], bh[c][3]);
                }
            }
        }
    }

    int g = lane >> 2, t4 = lane & 3;
    #pragma unroll
    for (int mt = 0; mt < 2; mt++) {
        #pragma unroll
        for (int nt = 0; nt < 4; nt++) {
            #pragma unroll
            for (int h8 = 0; h8 < 2; h8++) {
                float* d = acc[mt][nt * 2 + h8];
                int c0 = bn + wn * 64 + nt * 16 + h8 * 8 + t4 * 2;
                #pragma unroll
                for (int rr = 0; rr < 2; rr++) {
                    int r = bm + wm * 32 + mt * 16 + g + rr * 8;
                    size_t idx = (size_t)r * N + c0;
                    float v0 = d[rr * 2 + 0], v1 = d[rr * 2 + 1];
                    if (epi == 3) {
                        if (c0 < DMODEL) {
                            v0 = (v0 + __ldg(bias + c0)) * 0.125f;
                            v1 = (v1 + __ldg(bias + c0 + 1)) * 0.125f;
                        } else if (c0 < 2 * DMODEL) {
                            v0 += __ldg(bias2 + c0 - DMODEL);
                            v1 += __ldg(bias2 + c0 + 1 - DMODEL);
                        } else {
                            v0 += __ldg(bias3 + c0 - 2 * DMODEL);
                            v1 += __ldg(bias3 + c0 + 1 - 2 * DMODEL);
                        }
                        __nv_bfloat16 h0, l0, h1, l1;
                        split_bf16(v0, h0, l0); split_bf16(v1, h1, l1);
                        *(__nv_bfloat162*)&Chi[idx] = __nv_bfloat162(h0, h1);
                        *(__nv_bfloat162*)&Clo[idx] = __nv_bfloat162(l0, l1);
                        continue;
                    }
                    if (bias) {
                        v0 += __ldg(bias + c0);
                        v1 += __ldg(bias + c0 + 1);
                    }
                    if (epi == 4) {
                        float2 rr2 = *(const float2*)&resid[idx];
                        v0 += rr2.x; v1 += rr2.y;
                    } else if (epi == 2) {
                        v0 = 0.5f * v0 * (1.f + erff(v0 * 0.7071067811865476f));
                        v1 = 0.5f * v1 * (1.f + erff(v1 * 0.7071067811865476f));
                        __nv_bfloat16 h0, l0, h1, l1;
                        split_bf16(v0, h0, l0); split_bf16(v1, h1, l1);
                        *(__nv_bfloat162*)&Chi[idx] = __nv_bfloat162(h0, h1);
                        *(__nv_bfloat162*)&Clo[idx] = __nv_bfloat162(l0, l1);
                        continue;
                    }
                    float2 o; o.x = v0; o.y = v1;
                    *(float2*)&Cf[idx] = o;
                }
            }
        }
    }
}

// ---------------------------------------------------------------------------
// Sliding-window attention v7: mma flash attention on pre-split bf16 QKV;
// staging = pure copies; c-path and q-path merged into one launch.
// grid.x = 40: [0,32) c-blocks, [32,40) q-blocks.
// ---------------------------------------------------------------------------
#define AKOFF_LO 4608
#define AVOFF    9216
#define AQOFF_LO 9216

__global__ void __launch_bounds__(128, 3) local_attn_kernel(
    const __nv_bfloat16* __restrict__ Qhi, const __nv_bfloat16* __restrict__ Qlo,
    const int* __restrict__ c_mask, const int* __restrict__ q_mask,
    __nv_bfloat16* __restrict__ Ohi, __nv_bfloat16* __restrict__ Olo)
{
    __shared__ char  sbuf[18432];
    __shared__ float sbias[3 * CHUNK];
    __shared__ int   skpos[3 * CHUNK];

    int bx = blockIdx.x;
    int nb, nc, S, row_base; const int* mask;
    if (bx < 32) { nb = bx;      nc = 8; S = CLEN; row_base = 0;     mask = c_mask; }
    else         { nb = bx - 32; nc = 2; S = QLEN; row_base = QBASE; mask = q_mask; }
    int n = nb >> 2, qt = nb & 3;
    int h = blockIdx.y, b = blockIdx.z;
    int tid = threadIdx.x;
    int lane = tid & 31, w = tid >> 5;
    int g = lane >> 2, t4 = lane & 3;
    uint32_t sb32 = smem_u32(sbuf);

    #pragma unroll
    for (int jj = 0; jj < 6; jj++) {
        int j = tid + jj * 128;
        int cn = n - 1 + (j >> 8);
        bool cv = (cn >= 0) && (cn < nc);
        int cnc = min(max(cn, 0), nc - 1);
        int kpos = cnc * CHUNK + (j & 255);
        sbias[j] = (cv && mask[b * S + kpos] != 0) ? 0.f : -1e30f;
        skpos[j] = kpos;
    }

    // stage Q (pre-split): 64 rows x 64 dims, hi/lo, 144B pitch
    {
        int row = tid >> 1, half = tid & 1;
        size_t roff = (size_t)(row_base + b * S + n * CHUNK + qt * 64 + row) * NQKV
                    + h * DHEAD + half * 32;
        const uint4* sh = (const uint4*)(Qhi + roff);
        const uint4* sl = (const uint4*)(Qlo + roff);
        uint4 h0 = sh[0], h1 = sh[1], h2 = sh[2], h3 = sh[3];
        uint4 l0 = sl[0], l1 = sl[1], l2 = sl[2], l3 = sl[3];
        char* dst = sbuf + row * 144 + half * 64;
        *(uint4*)(dst +  0) = h0; *(uint4*)(dst + 16) = h1;
        *(uint4*)(dst + 32) = h2; *(uint4*)(dst + 48) = h3;
        *(uint4*)(dst + AQOFF_LO +  0) = l0; *(uint4*)(dst + AQOFF_LO + 16) = l1;
        *(uint4*)(dst + AQOFF_LO + 32) = l2; *(uint4*)(dst + AQOFF_LO + 48) = l3;
    }
    __syncthreads();

    uint32_t qh[4][4], ql[4][4];
    #pragma unroll
    for (int kc = 0; kc < 4; kc++) {
        uint32_t addr = sb32 + (uint32_t)((w * 16 + (lane & 15)) * 144 + kc * 32 + (lane >> 4) * 16);
        ldsm_x4(qh[kc], addr);
        ldsm_x4(ql[kc], addr + AQOFF_LO);
    }

    float m0 = -1e30f, m1 = -1e30f, l0s = 0.f, l1s = 0.f;
    float O[8][4] = {};

    int jlo = (n == 0) ? CHUNK : 0;
    int jhi = (n == nc - 1) ? (2 * CHUNK - 1) : (3 * CHUNK - 1);
    int wq0 = qt * 64 + w * 16;
    int wjs = max(wq0, jlo), wje = min(wq0 + 15 + WINW, jhi);
    int bjs = max(qt * 64, jlo), bje = min(qt * 64 + 63 + WINW, jhi);
    int iq0 = wq0 + g, iq1 = iq0 + 8;

    size_t kvbase = (size_t)(row_base + b * S) * NQKV + DMODEL + h * DHEAD;

    for (int t0 = bjs & ~31; t0 <= bje; t0 += 32) {
        __syncthreads();
        // stage K and V (pre-split copies), 144B pitch
        {
            int key = tid >> 2, dg = tid & 3;
            int j = min(t0 + key, 3 * CHUNK - 1);
            size_t roff = kvbase + (size_t)skpos[j] * NQKV + dg * 16;
            const uint4* kh = (const uint4*)(Qhi + roff);
            const uint4* kl = (const uint4*)(Qlo + roff);
            uint4 a0 = kh[0], a1 = kh[1], b0 = kl[0], b1 = kl[1];
            char* kd = sbuf + key * 144 + dg * 32;
            *(uint4*)(kd)                 = a0;
            *(uint4*)(kd + 16)            = a1;
            *(uint4*)(kd + AKOFF_LO)      = b0;
            *(uint4*)(kd + AKOFF_LO + 16) = b1;
            const uint4* vh = (const uint4*)(Qhi + roff + DMODEL);
            const uint4* vl = (const uint4*)(Qlo + roff + DMODEL);
            uint4 c0v = vh[0], c1v = vh[1], d0v = vl[0], d1v = vl[1];
            char* vd = sbuf + AVOFF + key * 144 + dg * 32;
            *(uint4*)(vd)               = c0v;
            *(uint4*)(vd + 16)          = c1v;
            *(uint4*)(vd + 4608)        = d0v;
            *(uint4*)(vd + 4608 + 16)   = d1v;
        }
        __syncthreads();

        if (t0 + 31 < wjs || t0 > wje) continue;

        // --- scores S[16 x 32] ---
        float Sc[4][4];
        #pragma unroll
        for (int tt = 0; tt < 4; tt++)
            #pragma unroll
            for (int e = 0; e < 4; e++) Sc[tt][e] = 0.f;

        #pragma unroll
        for (int kc = 0; kc < 4; kc++) {
            #pragma unroll
            for (int kh2 = 0; kh2 < 2; kh2++) {
                uint32_t bh[4], bl[4];
                uint32_t addr = sb32 + (uint32_t)((kh2 * 16 + (lane & 15)) * 144 + kc * 32 + (lane >> 4) * 16);
                ldsm_x4(bh, addr);
                ldsm_x4(bl, addr + AKOFF_LO);
                int t = kh2 * 2;
                mma_bf16(Sc[t],     qh[kc], bh[0], bh[2]);
                mma_bf16(Sc[t],     qh[kc], bl[0], bl[2]);
                mma_bf16(Sc[t],     ql[kc], bh[0], bh[2]);
                mma_bf16(Sc[t + 1], qh[kc], bh[1], bh[3]);
                mma_bf16(Sc[t + 1], qh[kc], bl[1], bl[3]);
                mma_bf16(Sc[t + 1], ql[kc], bh[1], bh[3]);
            }
        }

        // --- mask + row max ---
        float rm0 = -1e30f, rm1 = -1e30f;
        #pragma unroll
        for (int tt = 0; tt < 4; tt++) {
            int j0 = t0 + tt * 8 + 2 * t4, j1 = j0 + 1;
            float sb0 = sbias[min(j0, 3 * CHUNK - 1)];
            float sb1 = sbias[min(j1, 3 * CHUNK - 1)];
            bool v00 = (sb0 == 0.f) && (j0 >= iq0) && (j0 <= iq0 + WINW);
            bool v01 = (sb1 == 0.f) && (j1 >= iq0) && (j1 <= iq0 + WINW);
            bool v10 = (sb0 == 0.f) && (j0 >= iq1) && (j0 <= iq1 + WINW);
            bool v11 = (sb1 == 0.f) && (j1 >= iq1) && (j1 <= iq1 + WINW);
            Sc[tt][0] = v00 ? Sc[tt][0] : -1e30f;
            Sc[tt][1] = v01 ? Sc[tt][1] : -1e30f;
            Sc[tt][2] = v10 ? Sc[tt][2] : -1e30f;
            Sc[tt][3] = v11 ? Sc[tt][3] : -1e30f;
            rm0 = fmaxf(rm0, fmaxf(Sc[tt][0], Sc[tt][1]));
            rm1 = fmaxf(rm1, fmaxf(Sc[tt][2], Sc[tt][3]));
        }
        rm0 = fmaxf(rm0, __shfl_xor_sync(0xffffffffu, rm0, 1));
        rm0 = fmaxf(rm0, __shfl_xor_sync(0xffffffffu, rm0, 2));
        rm1 = fmaxf(rm1, __shfl_xor_sync(0xffffffffu, rm1, 1));
        rm1 = fmaxf(rm1, __shfl_xor_sync(0xffffffffu, rm1, 2));

        float mn0 = fmaxf(m0, rm0), mn1 = fmaxf(m1, rm1);
        float c0 = __expf(m0 - mn0), c1 = __expf(m1 - mn1);
        l0s *= c0; l1s *= c1;
        #pragma unroll
        for (int dt = 0; dt < 8; dt++) {
            O[dt][0] *= c0; O[dt][1] *= c0;
            O[dt][2] *= c1; O[dt][3] *= c1;
        }
        m0 = mn0; m1 = mn1;

        float rs0 = 0.f, rs1 = 0.f;
        #pragma unroll
        for (int tt = 0; tt < 4; tt++) {
            float p0 = (Sc[tt][0] > -5e29f) ? __expf(Sc[tt][0] - m0) : 0.f;
            float p1 = (Sc[tt][1] > -5e29f) ? __expf(Sc[tt][1] - m0) : 0.f;
            float p2 = (Sc[tt][2] > -5e29f) ? __expf(Sc[tt][2] - m1) : 0.f;
            float p3 = (Sc[tt][3] > -5e29f) ? __expf(Sc[tt][3] - m1) : 0.f;
            Sc[tt][0] = p0; Sc[tt][1] = p1; Sc[tt][2] = p2; Sc[tt][3] = p3;
            rs0 += p0 + p1; rs1 += p2 + p3;
        }
        rs0 += __shfl_xor_sync(0xffffffffu, rs0, 1);
        rs0 += __shfl_xor_sync(0xffffffffu, rs0, 2);
        rs1 += __shfl_xor_sync(0xffffffffu, rs1, 1);
        rs1 += __shfl_xor_sync(0xffffffffu, rs1, 2);
        l0s += rs0; l1s += rs1;

        // --- P @ V via trans-ldsm B fragments ---
        #pragma unroll
        for (int kc2 = 0; kc2 < 2; kc2++) {
            int ta = kc2 * 2, tb = ta + 1;
            uint32_t ah[4], al[4];
            split_pack2(Sc[ta][0], Sc[ta][1], ah[0], al[0]);
            split_pack2(Sc[ta][2], Sc[ta][3], ah[1], al[1]);
            split_pack2(Sc[tb][0], Sc[tb][1], ah[2], al[2]);
            split_pack2(Sc[tb][2], Sc[tb][3], ah[3], al[3]);
            uint32_t vrow = (uint32_t)(kc2 * 16 + (lane & 7) + ((lane & 16) ? 8 : 0));
            #pragma unroll
            for (int dt = 0; dt < 4; dt++) {
                uint32_t bh[4], bl[4];
                uint32_t addr = sb32 + AVOFF + vrow * 144
                              + (uint32_t)(dt * 32 + ((lane & 8) ? 16 : 0));
                ldsm_x4_trans(bh, addr);
                ldsm_x4_trans(bl, addr + 4608);
                mma_bf16(O[dt * 2],     ah, bh[0], bh[2]);
                mma_bf16(O[dt * 2],     ah, bl[0], bl[2]);
                mma_bf16(O[dt * 2],     al, bh[0], bh[2]);
                mma_bf16(O[dt * 2 + 1], ah, bh[1], bh[3]);
                mma_bf16(O[dt * 2 + 1], ah, bl[1], bl[3]);
                mma_bf16(O[dt * 2 + 1], al, bh[1], bh[3]);
            }
        }
    }

    float inv0 = 1.f / l0s, inv1 = 1.f / l1s;
    int qrow0 = row_base + b * S + n * CHUNK + wq0 + g;
    #pragma unroll
    for (int dt = 0; dt < 8; dt++) {
        int col = h * DHEAD + dt * 8 + 2 * t4;
        size_t i0 = (size_t)qrow0 * DMODEL + col;
        size_t i1 = i0 + (size_t)8 * DMODEL;
        float a0 = O[dt][0] * inv0, a1 = O[dt][1] * inv0;
        float b0 = O[dt][2] * inv1, b1 = O[dt][3] * inv1;
        __nv_bfloat16 h0, lo0, h1, lo1;
        split_bf16(a0, h0, lo0); split_bf16(a1, h1, lo1);
        *(__nv_bfloat162*)&Ohi[i0] = __nv_bfloat162(h0, h1);
        *(__nv_bfloat162*)&Olo[i0] = __nv_bfloat162(lo0, lo1);
        split_bf16(b0, h0, lo0); split_bf16(b1, h1, lo1);
        *(__nv_bfloat162*)&Ohi[i1] = __nv_bfloat162(h0, h1);
        *(__nv_bfloat162*)&Olo[i1] = __nv_bfloat162(lo0, lo1);
    }
}

// ---------------------------------------------------------------------------
// Interaction head
// ---------------------------------------------------------------------------
__global__ void init_re_kernel(float* __restrict__ re)
{
    re[blockIdx.x * 256 + threadIdx.x] = 0.f;
}

__global__ void __launch_bounds__(256) softmax_max_kernel(
    const float* __restrict__ P, float* __restrict__ re)
{
    int row = blockIdx.x, tid = threadIdx.x;
    int b = row / CLEN;
    const float* p = P + (size_t)row * QLEN;
    float x0 = p[tid], x1 = p[tid + 256];
    float m = block_reduce_max(fmaxf(x0, x1));
    float e0 = __expf(x0 - m), e1 = __expf(x1 - m);
    float s = block_reduce_sum(e0 + e1);
    float inv = 1.f / s;
    unsigned* r = (unsigned*)(re + b * QLEN);
    atomicMax(r + tid,       __float_as_uint(e0 * inv));
    atomicMax(r + tid + 256, __float_as_uint(e1 * inv));
}

__global__ void fc_kernel(const float* __restrict__ re, const float* __restrict__ w,
                          const float* __restrict__ bfc, float* __restrict__ out)
{
    int t = threadIdx.x;
    if (t >= 8) return;
    int b = t >> 2, o = t & 3;
    float s = bfc[o];
    for (int q = 0; q < QLEN; q++) s += re[b * QLEN + q] * w[q * 4 + o];
    out[b * 4 + o] = s;
}

// ---------------------------------------------------------------------------
// Host orchestration
// ---------------------------------------------------------------------------
extern "C" void kernel_launch(void* const* d_in, const int* in_sizes, int n_in,
                              void* d_out, int out_size)
{
    const int*   q_ids    = (const int*)  d_in[0];
    const int*   c_ids    = (const int*)  d_in[1];
    const int*   q_mask   = (const int*)  d_in[2];
    const int*   c_mask   = (const int*)  d_in[3];
    const float* word_emb = (const float*)d_in[4];
    const float* pos_emb  = (const float*)d_in[5];
    const float* type_emb = (const float*)d_in[6];
    const float* eg       = (const float*)d_in[7];
    const float* eb       = (const float*)d_in[8];
    const float* Wq  = (const float*)d_in[9];
    const float* bq  = (const float*)d_in[10];
    const float* Wk  = (const float*)d_in[11];
    const float* bk  = (const float*)d_in[12];
    const float* Wv  = (const float*)d_in[13];
    const float* bv  = (const float*)d_in[14];
    const float* Wo  = (const float*)d_in[15];
    const float* bo  = (const float*)d_in[16];
    const float* l1g = (const float*)d_in[17];
    const float* l1b = (const float*)d_in[18];
    const float* W1  = (const float*)d_in[19];
    const float* b1  = (const float*)d_in[20];
    const float* W2  = (const float*)d_in[21];
    const float* b2  = (const float*)d_in[22];
    const float* l2g = (const float*)d_in[23];
    const float* l2b = (const float*)d_in[24];
    const float* fcw = (const float*)d_in[25];
    const float* fcb = (const float*)d_in[26];

    cudaFuncSetAttribute(mma_gemm, cudaFuncAttributeMaxDynamicSharedMemorySize, SMEMSZ);

    __nv_bfloat16 *wqkvhi, *wqkvlo, *wohi, *wolo, *w1hi, *w1lo, *w2hi, *w2lo;
    __nv_bfloat16 *hhi, *hlo, *sthi, *stlo, *ffnhi, *ffnlo, *qkvhi, *qkvlo;
    float *h, *t2, *ssc, *sre;
    cudaGetSymbolAddress((void**)&wqkvhi, g_wqkv_hi);
    cudaGetSymbolAddress((void**)&wqkvlo, g_wqkv_lo);
    cudaGetSymbolAddress((void**)&wohi,   g_wo_hi);
    cudaGetSymbolAddress((void**)&wolo,   g_wo_lo);
    cudaGetSymbolAddress((void**)&w1hi,   g_w1_hi);
    cudaGetSymbolAddress((void**)&w1lo,   g_w1_lo);
    cudaGetSymbolAddress((void**)&w2hi,   g_w2_hi);
    cudaGetSymbolAddress((void**)&w2lo,   g_w2_lo);
    cudaGetSymbolAddress((void**)&h,      g_h);
    cudaGetSymbolAddress((void**)&hhi,    g_h_hi);
    cudaGetSymbolAddress((void**)&hlo,    g_h_lo);
    cudaGetSymbolAddress((void**)&qkvhi,  g_qkv_hi);
    cudaGetSymbolAddress((void**)&qkvlo,  g_qkv_lo);
    cudaGetSymbolAddress((void**)&t2,     g_t2);
    cudaGetSymbolAddress((void**)&sthi,   g_st_hi);
    cudaGetSymbolAddress((void**)&stlo,   g_st_lo);
    cudaGetSymbolAddress((void**)&ffnhi,  g_ffn_hi);
    cudaGetSymbolAddress((void**)&ffnlo,  g_ffn_lo);
    cudaGetSymbolAddress((void**)&ssc,    g_sc);
    cudaGetSymbolAddress((void**)&sre,    g_re);

    dim3 gQKV(NQKV/128,   ROWSA/128);
    dim3 gD  (DMODEL/128, ROWSA/128);
    dim3 gF  (FFDIM/128,  ROWSA/128);
    dim3 gA(40, NHEAD, BATCH);          // merged c(32) + q(8) attention blocks

    // 0: QKV weight prep
    wprep_qkv_all<<<dim3(24, 24, 36), 256>>>(Wq, Wk, Wv, wqkvhi, wqkvlo);
    // 1: merged embedding
    embed_ln_all<<<ROWSA, 256>>>(c_ids, q_ids, word_emb, pos_emb, type_emb,
                                 eg, eb, h, hhi, hlo);
    // 2: Wo prep (keeps idx 3 = GEMM for the profiler)
    wprep_b<<<dim3(24, 24, NL), 256>>>(Wo, wohi, wolo, DMODEL, DMODEL);
    // 3: layer-0 QKV GEMM (profiling target)
    mma_gemm<<<gQKV, 256, SMEMSZ>>>(hhi, hlo, wqkvhi, wqkvlo,
        bq, bk, bv, nullptr, nullptr, qkvhi, qkvlo, ROWSA, NQKV, DMODEL, 3);
    // 4: layer-0 merged attention
    local_attn_kernel<<<gA, 128>>>(qkvhi, qkvlo, c_mask, q_mask, sthi, stlo);
    // 5-6: remaining weight prep
    wprep_b<<<dim3(96, 24, NL), 256>>>(W1, w1hi, w1lo, DMODEL, FFDIM);
    wprep_b<<<dim3(24, 96, NL), 256>>>(W2, w2hi, w2lo, FFDIM, DMODEL);

    for (int l = 0; l < NL; l++) {
        if (l > 0) {
            size_t qb = (size_t)l * QKVW;
            mma_gemm<<<gQKV, 256, SMEMSZ>>>(hhi, hlo, wqkvhi + qb, wqkvlo + qb,
                bq + l*DMODEL, bk + l*DMODEL, bv + l*DMODEL, nullptr,
                nullptr, qkvhi, qkvlo, ROWSA, NQKV, DMODEL, 3);
            local_attn_kernel<<<gA, 128>>>(qkvhi, qkvlo, c_mask, q_mask, sthi, stlo);
        }
        // t2 = h + attnout @ Wo + bo   (residual fused in epilogue)
        mma_gemm<<<gD, 256, SMEMSZ>>>(sthi, stlo, wohi + l*D2, wolo + l*D2,
            bo + l*DMODEL, nullptr, nullptr, h, t2, nullptr, nullptr,
            ROWSA, DMODEL, DMODEL, 4);
        add_ln_kernel<<<ROWSA, 256>>>(h, t2, l1g + l*DMODEL, l1b + l*DMODEL, hhi, hlo);
        mma_gemm<<<gF, 256, SMEMSZ>>>(hhi, hlo, w1hi + l*DF, w1lo + l*DF,
            b1 + l*FFDIM, nullptr, nullptr, nullptr, nullptr, ffnhi, ffnlo,
            ROWSA, FFDIM, DMODEL, 2);
        // t2 = h + ffn @ W2 + b2
        mma_gemm<<<gD, 256, SMEMSZ>>>(ffnhi, ffnlo, w2hi + l*DF, w2lo + l*DF,
            b2 + l*DMODEL, nullptr, nullptr, h, t2, nullptr, nullptr,
            ROWSA, DMODEL, FFDIM, 4);
        add_ln_kernel<<<ROWSA, 256>>>(h, t2, l2g + l*DMODEL, l2b + l*DMODEL, hhi, hlo);
    }

    // interaction
    for (int b = 0; b < BATCH; b++) {
        mma_gemm<<<dim3(QLEN/128, CLEN/128), 256, SMEMSZ>>>(
            hhi + (size_t)b*CLEN*DMODEL, hlo + (size_t)b*CLEN*DMODEL,
            hhi + (size_t)(QBASE + b*QLEN)*DMODEL, hlo + (size_t)(QBASE + b*QLEN)*DMODEL,
            nullptr, nullptr, nullptr, nullptr,
            ssc + (size_t)b*CLEN*QLEN, nullptr, nullptr,
            CLEN, QLEN, DMODEL, 0);
    }
    init_re_kernel<<<BATCH * QLEN / 256, 256>>>(sre);
    softmax_max_kernel<<<BATCH * CLEN, 256>>>(ssc, sre);
    fc_kernel<<<1, 32>>>(sre, fcw, fcb, (float*)d_out);
}